// round 2
// baseline (speedup 1.0000x reference)
#include <cuda_runtime.h>
#include <math.h>

#define NB   2
#define SEQ  2048
#define HID  2048
#define NH   16
#define HD   128
#define MROWS (NB*SEQ)   /* 4096 */

// scratch (allocation-free: device globals)
__device__ float g_qbuf[(size_t)MROWS * HID];   // 32 MB: q after proj+rope, [b,s,h,d]
__device__ float g_obuf[(size_t)MROWS * HID];   // 32 MB: attention out, [b,s,h,d]
__device__ float g_kvfb[(size_t)2 * MROWS * HD]; // fallback if out buffer lacks k/v space

// ---------------------------------------------------------------------------
// SGEMM NT: C[M,N] = A[M,K] * B[N,K]^T   (both row-major, K contiguous)
// 128x128 block tile, BK=8, 256 threads, 8x8 micro-tile per thread.
// All dims are multiples of the tiles for this problem (M=4096, N in {2048,128}, K=2048).
// ---------------------------------------------------------------------------
#define BM 128
#define BN 128
#define BK 8

__global__ __launch_bounds__(256) void sgemm_nt(const float* __restrict__ A,
                                                const float* __restrict__ B,
                                                float* __restrict__ C,
                                                int M, int N, int K) {
    __shared__ float As[BK][BM];
    __shared__ float Bs[BK][BN];
    const int tid  = threadIdx.x;
    const int tx   = tid & 15;        // n-dir (16 threads * 8 cols)
    const int ty   = tid >> 4;        // m-dir (16 threads * 8 rows)
    const int arow = tid >> 1;        // 0..127
    const int ac4  = (tid & 1) * 4;   // 0 or 4

    const float* Ab = A + (size_t)blockIdx.y * BM * K;
    const float* Bb = B + (size_t)blockIdx.x * BN * K;

    float acc[8][8];
#pragma unroll
    for (int i = 0; i < 8; i++)
#pragma unroll
        for (int j = 0; j < 8; j++) acc[i][j] = 0.f;

    for (int k0 = 0; k0 < K; k0 += BK) {
        float4 av = *(const float4*)(Ab + (size_t)arow * K + k0 + ac4);
        float4 bv = *(const float4*)(Bb + (size_t)arow * K + k0 + ac4);
        __syncthreads();
        As[ac4 + 0][arow] = av.x; As[ac4 + 1][arow] = av.y;
        As[ac4 + 2][arow] = av.z; As[ac4 + 3][arow] = av.w;
        Bs[ac4 + 0][arow] = bv.x; Bs[ac4 + 1][arow] = bv.y;
        Bs[ac4 + 2][arow] = bv.z; Bs[ac4 + 3][arow] = bv.w;
        __syncthreads();
#pragma unroll
        for (int k = 0; k < BK; k++) {
            float a[8], b[8];
#pragma unroll
            for (int i = 0; i < 8; i++) a[i] = As[k][ty * 8 + i];
#pragma unroll
            for (int j = 0; j < 8; j++) b[j] = Bs[k][tx * 8 + j];
#pragma unroll
            for (int i = 0; i < 8; i++)
#pragma unroll
                for (int j = 0; j < 8; j++)
                    acc[i][j] = fmaf(a[i], b[j], acc[i][j]);
        }
    }

    float* Cb = C + (size_t)(blockIdx.y * BM + ty * 8) * N + blockIdx.x * BN + tx * 8;
#pragma unroll
    for (int i = 0; i < 8; i++) {
#pragma unroll
        for (int j4 = 0; j4 < 2; j4++) {
            float4 o;
            o.x = acc[i][j4 * 4 + 0]; o.y = acc[i][j4 * 4 + 1];
            o.z = acc[i][j4 * 4 + 2]; o.w = acc[i][j4 * 4 + 3];
            *(float4*)(Cb + (size_t)i * N + j4 * 4) = o;
        }
    }
}

// ---------------------------------------------------------------------------
// RoPE.  emb[s, d] = s * invfreq[d mod 64];  invfreq[j] = 10000^(-j/64)
// q'[j] = q[j]*cos - q[j+64]*sin ; q'[j+64] = q[j+64]*cos + q[j]*sin
// Q additionally gets the 1/sqrt(hd) softmax scale folded in.
// ---------------------------------------------------------------------------
#define LOG2_10000_DIV64 0.20762050593f
#define QSCALE 0.08838834765f   /* 1/sqrt(128) */

__global__ void rope_q_kernel(float* __restrict__ q) {
    // grid (MROWS, NH), block 64
    const int bs = blockIdx.x;          // b*SEQ + s
    const int h  = blockIdx.y;
    const int j  = threadIdx.x;         // 0..63
    const int s  = bs & (SEQ - 1);
    float inv = exp2f(-(float)j * LOG2_10000_DIV64);
    float sn, cs;
    sincosf((float)s * inv, &sn, &cs);
    float* row = q + ((size_t)bs * NH + h) * HD;
    float x1 = row[j], x2 = row[j + 64];
    row[j]      = (x1 * cs - x2 * sn) * QSCALE;
    row[j + 64] = (x2 * cs + x1 * sn) * QSCALE;
}

__global__ void rope_k_kernel(float* __restrict__ k) {
    // grid MROWS, block 64
    const int bs = blockIdx.x;
    const int j  = threadIdx.x;
    const int s  = bs & (SEQ - 1);
    float inv = exp2f(-(float)j * LOG2_10000_DIV64);
    float sn, cs;
    sincosf((float)s * inv, &sn, &cs);
    float* row = k + (size_t)bs * HD;
    float x1 = row[j], x2 = row[j + 64];
    row[j]      = x1 * cs - x2 * sn;
    row[j + 64] = x2 * cs + x1 * sn;
}

// ---------------------------------------------------------------------------
// Flash attention, fp32, single KV head.
// Block: 128 threads (4 warps), 64 query rows (warp w owns rows w*16..w*16+15),
// key tiles of 32.  Lane owns one key (scores) / one 4-wide d-slice (output).
// ---------------------------------------------------------------------------
#define TQ 64
#define TK 32
#define KSTR 132          /* padded row stride for K/V smem (floats) */
#define FLASH_SMEM ((TQ*HD + 2*TK*KSTR) * 4)   /* 66560 bytes */

__global__ __launch_bounds__(128) void flash_kernel(const float* __restrict__ qb,
                                                    const float* __restrict__ kb,
                                                    const float* __restrict__ vb,
                                                    float* __restrict__ ob) {
    extern __shared__ float sm[];
    float* q_sh = sm;                    // TQ * HD
    float* k_sh = sm + TQ * HD;          // TK * KSTR
    float* v_sh = k_sh + TK * KSTR;      // TK * KSTR

    const int b = blockIdx.z, h = blockIdx.y, qt = blockIdx.x;
    const int tid = threadIdx.x, w = tid >> 5, lane = tid & 31;

    // load Q tile [TQ x HD]
    for (int i = tid; i < TQ * HD / 4; i += 128) {
        int r = i >> 5, c4 = (i & 31) << 2;
        float4 t = *(const float4*)(qb + ((size_t)(b * SEQ + qt * TQ + r) * NH + h) * HD + c4);
        *(float4*)(q_sh + r * HD + c4) = t;
    }

    float acc[16][4];
    float mrow[16], lrow[16];
#pragma unroll
    for (int r = 0; r < 16; r++) {
        mrow[r] = -1e30f; lrow[r] = 0.f;
#pragma unroll
        for (int c = 0; c < 4; c++) acc[r][c] = 0.f;
    }

    for (int kt = 0; kt < SEQ / TK; kt++) {
        __syncthreads();
        // load K, V tiles [TK x HD]
        for (int i = tid; i < TK * HD / 4; i += 128) {
            int r = i >> 5, c4 = (i & 31) << 2;
            size_t g = (size_t)(b * SEQ + kt * TK + r) * HD + c4;
            *(float4*)(k_sh + r * KSTR + c4) = *(const float4*)(kb + g);
            *(float4*)(v_sh + r * KSTR + c4) = *(const float4*)(vb + g);
        }
        __syncthreads();

        // scores: lane owns key j = lane; s[r] = q_row . k_lane  (scale pre-folded into q)
        float s[16];
#pragma unroll
        for (int r = 0; r < 16; r++) s[r] = 0.f;
        const float* krow = k_sh + lane * KSTR;
#pragma unroll 4
        for (int d4 = 0; d4 < 32; d4++) {
            float4 k4 = *(const float4*)(krow + d4 * 4);
#pragma unroll
            for (int r = 0; r < 16; r++) {
                float4 q4 = *(const float4*)(q_sh + (w * 16 + r) * HD + d4 * 4);
                s[r] += q4.x * k4.x + q4.y * k4.y + q4.z * k4.z + q4.w * k4.w;
            }
        }

        // online softmax update (per row)
        float p[16];
#pragma unroll
        for (int r = 0; r < 16; r++) {
            float mx = s[r];
#pragma unroll
            for (int o = 16; o > 0; o >>= 1) mx = fmaxf(mx, __shfl_xor_sync(0xffffffffu, mx, o));
            float mnew = fmaxf(mrow[r], mx);
            float pe = __expf(s[r] - mnew);
            float ps = pe;
#pragma unroll
            for (int o = 16; o > 0; o >>= 1) ps += __shfl_xor_sync(0xffffffffu, ps, o);
            float corr = __expf(mrow[r] - mnew);
            lrow[r] = lrow[r] * corr + ps;
            mrow[r] = mnew;
            p[r] = pe;
#pragma unroll
            for (int c = 0; c < 4; c++) acc[r][c] *= corr;
        }

        // AV: acc[r][*] += sum_j p[r][j] * v[j][lane*4..]
#pragma unroll 4
        for (int jj = 0; jj < TK; jj++) {
            float4 v4 = *(const float4*)(v_sh + jj * KSTR + lane * 4);
#pragma unroll
            for (int r = 0; r < 16; r++) {
                float pv = __shfl_sync(0xffffffffu, p[r], jj);
                acc[r][0] += pv * v4.x; acc[r][1] += pv * v4.y;
                acc[r][2] += pv * v4.z; acc[r][3] += pv * v4.w;
            }
        }
    }

    // write out: ob[b, s, h, d]
#pragma unroll
    for (int r = 0; r < 16; r++) {
        float invl = 1.f / lrow[r];
        int sq = qt * TQ + w * 16 + r;
        float4 o4;
        o4.x = acc[r][0] * invl; o4.y = acc[r][1] * invl;
        o4.z = acc[r][2] * invl; o4.w = acc[r][3] * invl;
        *(float4*)(ob + ((size_t)(b * SEQ + sq) * NH + h) * HD + lane * 4) = o4;
    }
}

// ---------------------------------------------------------------------------
extern "C" void kernel_launch(void* const* d_in, const int* in_sizes, int n_in,
                              void* d_out, int out_size) {
    const float* x  = (const float*)d_in[0];   // [B,S,H]
    const float* Wq = (const float*)d_in[1];   // [H,H]
    const float* Wk = (const float*)d_in[2];   // [hd,H]
    const float* Wv = (const float*)d_in[3];   // [hd,H]
    const float* Wo = (const float*)d_in[4];   // [H,H]
    float* out = (float*)d_out;

    float* qbuf; cudaGetSymbolAddress((void**)&qbuf, g_qbuf);
    float* obuf; cudaGetSymbolAddress((void**)&obuf, g_obuf);
    float* kvfb; cudaGetSymbolAddress((void**)&kvfb, g_kvfb);

    const size_t off_k = (size_t)MROWS * HID;                // attn_output elems
    const size_t off_v = off_k + (size_t)MROWS * HD;
    const size_t need  = off_v + (size_t)MROWS * HD;         // 9437184

    float* kout;
    float* vout;
    if ((size_t)out_size >= need) {           // k, v returned in d_out after attn
        kout = out + off_k;
        vout = out + off_v;
    } else {                                  // safety: keep k/v in scratch
        kout = kvfb;
        vout = kvfb + (size_t)MROWS * HD;
    }

    cudaFuncSetAttribute(flash_kernel, cudaFuncAttributeMaxDynamicSharedMemorySize,
                         FLASH_SMEM);

    dim3 gbig(HID / BN, MROWS / BM);   // (16, 32)
    dim3 gkv (HD  / BN, MROWS / BM);   // (1, 32)

    sgemm_nt<<<gbig, 256>>>(x, Wq, qbuf, MROWS, HID, HID);
    sgemm_nt<<<gkv,  256>>>(x, Wk, kout, MROWS, HD,  HID);
    sgemm_nt<<<gkv,  256>>>(x, Wv, vout, MROWS, HD,  HID);

    rope_q_kernel<<<dim3(MROWS, NH), 64>>>(qbuf);
    rope_k_kernel<<<MROWS, 64>>>(kout);

    flash_kernel<<<dim3(SEQ / TQ, NH, NB), 128, FLASH_SMEM>>>(qbuf, kout, vout, obuf);

    sgemm_nt<<<gbig, 256>>>(obuf, Wo, out, MROWS, HID, HID);
}

// round 4
// speedup vs baseline: 1.6149x; 1.6149x over previous
#include <cuda_runtime.h>
#include <math.h>
#include <stdint.h>

#define NB   2
#define SEQ  2048
#define HID  2048
#define NH   16
#define HD   128
#define MROWS (NB*SEQ)   /* 4096 */

// scratch (allocation-free: device globals)
__device__ float g_qbuf[(size_t)MROWS * HID];   // q after proj+rope, [b,s,h,d]
__device__ float g_obuf[(size_t)MROWS * HID];   // attention out, [b,s,h,d]
__device__ float g_kvfb[(size_t)2 * MROWS * HD];

// ===========================================================================
// TF32 tensor-core GEMM NT: C[M,N] = A[M,K] * B[N,K]^T (row-major, K contig)
// CTA tile 128x128x32, 256 threads = 8 warps (4 m x 2 n), warp tile 32x64.
// mma.sync.m16n8k8.tf32, cp.async double-buffered smem, +4 float row pad.
// ===========================================================================
#define GPAD 36                 /* 32 + 4 floats per smem row */
#define STAGE_FLOATS (2 * 128 * GPAD)   /* As + Bs per stage = 9216 */
#define GEMM_SMEM (2 * STAGE_FLOATS * 4) /* 73728 bytes */

__device__ __forceinline__ uint32_t f2tf32(float x) {
    uint32_t r;
    asm("cvt.rna.tf32.f32 %0, %1;" : "=r"(r) : "f"(x));
    return r;
}
__device__ __forceinline__ void cp_async16(uint32_t s, const void* g) {
    asm volatile("cp.async.cg.shared.global [%0], [%1], 16;\n" :: "r"(s), "l"(g));
}

__device__ __forceinline__ void gemm_body(const float* __restrict__ A,
                                          const float* __restrict__ Bw,
                                          float* __restrict__ C,
                                          int N, int K, int bm, int bn) {
    extern __shared__ float sm[];
    const int tid  = threadIdx.x;
    const int wid  = tid >> 5, lane = tid & 31;
    const int g    = lane >> 2, t = lane & 3;
    const int wm   = (wid & 3) * 32;
    const int wn   = (wid >> 2) * 64;

    const float* Ab = A  + (size_t)bm * 128 * K;
    const float* Bb = Bw + (size_t)bn * 128 * K;

    float acc[2][8][4];
#pragma unroll
    for (int mt = 0; mt < 2; mt++)
#pragma unroll
        for (int nt = 0; nt < 8; nt++)
#pragma unroll
            for (int c = 0; c < 4; c++) acc[mt][nt][c] = 0.f;

    const uint32_t smb = (uint32_t)__cvta_generic_to_shared(sm);
    const int NKI = K >> 5;

    // prefetch tile 0
    {
        uint32_t As_s = smb, Bs_s = smb + 128 * GPAD * 4;
#pragma unroll
        for (int i = 0; i < 4; i++) {
            int e = tid + i * 256, row = e >> 3, c4 = (e & 7) * 4;
            cp_async16(As_s + (row * GPAD + c4) * 4, Ab + (size_t)row * K + c4);
            cp_async16(Bs_s + (row * GPAD + c4) * 4, Bb + (size_t)row * K + c4);
        }
        asm volatile("cp.async.commit_group;\n");
    }

    for (int ki = 0; ki < NKI; ki++) {
        if (ki + 1 < NKI) {
            int s = (ki + 1) & 1;
            uint32_t As_s = smb + s * STAGE_FLOATS * 4;
            uint32_t Bs_s = As_s + 128 * GPAD * 4;
            const float* Ag = Ab + (ki + 1) * 32;
            const float* Bg = Bb + (ki + 1) * 32;
#pragma unroll
            for (int i = 0; i < 4; i++) {
                int e = tid + i * 256, row = e >> 3, c4 = (e & 7) * 4;
                cp_async16(As_s + (row * GPAD + c4) * 4, Ag + (size_t)row * K + c4);
                cp_async16(Bs_s + (row * GPAD + c4) * 4, Bg + (size_t)row * K + c4);
            }
            asm volatile("cp.async.commit_group;\n");
            asm volatile("cp.async.wait_group 1;\n");
        } else {
            asm volatile("cp.async.wait_group 0;\n");
        }
        __syncthreads();

        const float* As = sm + (ki & 1) * STAGE_FLOATS;
        const float* Bs = As + 128 * GPAD;

#pragma unroll
        for (int kk = 0; kk < 4; kk++) {
            uint32_t a[2][4], b[8][2];
            const int k = kk * 8 + t;
#pragma unroll
            for (int mt = 0; mt < 2; mt++) {
                int r = wm + mt * 16 + g;
                a[mt][0] = f2tf32(As[r * GPAD + k]);
                a[mt][1] = f2tf32(As[(r + 8) * GPAD + k]);
                a[mt][2] = f2tf32(As[r * GPAD + k + 4]);
                a[mt][3] = f2tf32(As[(r + 8) * GPAD + k + 4]);
            }
#pragma unroll
            for (int nt = 0; nt < 8; nt++) {
                int n = wn + nt * 8 + g;
                b[nt][0] = f2tf32(Bs[n * GPAD + k]);
                b[nt][1] = f2tf32(Bs[n * GPAD + k + 4]);
            }
#pragma unroll
            for (int mt = 0; mt < 2; mt++)
#pragma unroll
                for (int nt = 0; nt < 8; nt++) {
                    asm volatile(
                        "mma.sync.aligned.m16n8k8.row.col.f32.tf32.tf32.f32 "
                        "{%0,%1,%2,%3}, {%4,%5,%6,%7}, {%8,%9}, {%0,%1,%2,%3};\n"
                        : "+f"(acc[mt][nt][0]), "+f"(acc[mt][nt][1]),
                          "+f"(acc[mt][nt][2]), "+f"(acc[mt][nt][3])
                        : "r"(a[mt][0]), "r"(a[mt][1]), "r"(a[mt][2]), "r"(a[mt][3]),
                          "r"(b[nt][0]), "r"(b[nt][1]));
                }
        }
        __syncthreads();
    }

    // epilogue: c0:(g,2t) c1:(g,2t+1) c2:(g+8,2t) c3:(g+8,2t+1)
#pragma unroll
    for (int mt = 0; mt < 2; mt++) {
        int r0 = bm * 128 + wm + mt * 16 + g;
#pragma unroll
        for (int nt = 0; nt < 8; nt++) {
            int c0 = bn * 128 + wn + nt * 8 + t * 2;
            float2 v0 = make_float2(acc[mt][nt][0], acc[mt][nt][1]);
            float2 v1 = make_float2(acc[mt][nt][2], acc[mt][nt][3]);
            *(float2*)(C + (size_t)r0 * N + c0)       = v0;
            *(float2*)(C + (size_t)(r0 + 8) * N + c0) = v1;
        }
    }
}

__global__ __launch_bounds__(256) void tf32_gemm(const float* __restrict__ A,
                                                 const float* __restrict__ B,
                                                 float* __restrict__ C,
                                                 int N, int K) {
    gemm_body(A, B, C, N, K, blockIdx.y, blockIdx.x);
}

__global__ __launch_bounds__(256) void tf32_gemm_kv(const float* __restrict__ A,
                                                    const float* __restrict__ Bk,
                                                    const float* __restrict__ Bv,
                                                    float* __restrict__ Ck,
                                                    float* __restrict__ Cv,
                                                    int K) {
    if (blockIdx.z == 0) gemm_body(A, Bk, Ck, HD, K, blockIdx.y, 0);
    else                 gemm_body(A, Bv, Cv, HD, K, blockIdx.y, 0);
}

// ---------------------------------------------------------------------------
// RoPE
// ---------------------------------------------------------------------------
#define LOG2_10000_DIV64 0.20762050593f
#define QSCALE 0.08838834765f   /* 1/sqrt(128) */

__global__ void rope_q_kernel(float* __restrict__ q) {
    const int bs = blockIdx.x;
    const int h  = blockIdx.y;
    const int j  = threadIdx.x;
    const int s  = bs & (SEQ - 1);
    float inv = exp2f(-(float)j * LOG2_10000_DIV64);
    float sn, cs;
    sincosf((float)s * inv, &sn, &cs);
    float* row = q + ((size_t)bs * NH + h) * HD;
    float x1 = row[j], x2 = row[j + 64];
    row[j]      = (x1 * cs - x2 * sn) * QSCALE;
    row[j + 64] = (x2 * cs + x1 * sn) * QSCALE;
}

__global__ void rope_k_kernel(float* __restrict__ k) {
    const int bs = blockIdx.x;
    const int j  = threadIdx.x;
    const int s  = bs & (SEQ - 1);
    float inv = exp2f(-(float)j * LOG2_10000_DIV64);
    float sn, cs;
    sincosf((float)s * inv, &sn, &cs);
    float* row = k + (size_t)bs * HD;
    float x1 = row[j], x2 = row[j + 64];
    row[j]      = x1 * cs - x2 * sn;
    row[j + 64] = x2 * cs + x1 * sn;
}

// ---------------------------------------------------------------------------
// Flash attention, fp32, single KV head (unchanged from R2)
// ---------------------------------------------------------------------------
#define TQ 64
#define TK 32
#define KSTR 132
#define FLASH_SMEM ((TQ*HD + 2*TK*KSTR) * 4)

__global__ __launch_bounds__(128) void flash_kernel(const float* __restrict__ qb,
                                                    const float* __restrict__ kb,
                                                    const float* __restrict__ vb,
                                                    float* __restrict__ ob) {
    extern __shared__ float smf[];
    float* q_sh = smf;
    float* k_sh = smf + TQ * HD;
    float* v_sh = k_sh + TK * KSTR;

    const int b = blockIdx.z, h = blockIdx.y, qt = blockIdx.x;
    const int tid = threadIdx.x, w = tid >> 5, lane = tid & 31;

    for (int i = tid; i < TQ * HD / 4; i += 128) {
        int r = i >> 5, c4 = (i & 31) << 2;
        float4 tq = *(const float4*)(qb + ((size_t)(b * SEQ + qt * TQ + r) * NH + h) * HD + c4);
        *(float4*)(q_sh + r * HD + c4) = tq;
    }

    float acc[16][4];
    float mrow[16], lrow[16];
#pragma unroll
    for (int r = 0; r < 16; r++) {
        mrow[r] = -1e30f; lrow[r] = 0.f;
#pragma unroll
        for (int c = 0; c < 4; c++) acc[r][c] = 0.f;
    }

    for (int kt = 0; kt < SEQ / TK; kt++) {
        __syncthreads();
        for (int i = tid; i < TK * HD / 4; i += 128) {
            int r = i >> 5, c4 = (i & 31) << 2;
            size_t gg = (size_t)(b * SEQ + kt * TK + r) * HD + c4;
            *(float4*)(k_sh + r * KSTR + c4) = *(const float4*)(kb + gg);
            *(float4*)(v_sh + r * KSTR + c4) = *(const float4*)(vb + gg);
        }
        __syncthreads();

        float s[16];
#pragma unroll
        for (int r = 0; r < 16; r++) s[r] = 0.f;
        const float* krow = k_sh + lane * KSTR;
#pragma unroll 4
        for (int d4 = 0; d4 < 32; d4++) {
            float4 k4 = *(const float4*)(krow + d4 * 4);
#pragma unroll
            for (int r = 0; r < 16; r++) {
                float4 q4 = *(const float4*)(q_sh + (w * 16 + r) * HD + d4 * 4);
                s[r] += q4.x * k4.x + q4.y * k4.y + q4.z * k4.z + q4.w * k4.w;
            }
        }

        float p[16];
#pragma unroll
        for (int r = 0; r < 16; r++) {
            float mx = s[r];
#pragma unroll
            for (int o = 16; o > 0; o >>= 1) mx = fmaxf(mx, __shfl_xor_sync(0xffffffffu, mx, o));
            float mnew = fmaxf(mrow[r], mx);
            float pe = __expf(s[r] - mnew);
            float ps = pe;
#pragma unroll
            for (int o = 16; o > 0; o >>= 1) ps += __shfl_xor_sync(0xffffffffu, ps, o);
            float corr = __expf(mrow[r] - mnew);
            lrow[r] = lrow[r] * corr + ps;
            mrow[r] = mnew;
            p[r] = pe;
#pragma unroll
            for (int c = 0; c < 4; c++) acc[r][c] *= corr;
        }

#pragma unroll 4
        for (int jj = 0; jj < TK; jj++) {
            float4 v4 = *(const float4*)(v_sh + jj * KSTR + lane * 4);
#pragma unroll
            for (int r = 0; r < 16; r++) {
                float pv = __shfl_sync(0xffffffffu, p[r], jj);
                acc[r][0] += pv * v4.x; acc[r][1] += pv * v4.y;
                acc[r][2] += pv * v4.z; acc[r][3] += pv * v4.w;
            }
        }
    }

#pragma unroll
    for (int r = 0; r < 16; r++) {
        float invl = 1.f / lrow[r];
        int sq = qt * TQ + w * 16 + r;
        float4 o4;
        o4.x = acc[r][0] * invl; o4.y = acc[r][1] * invl;
        o4.z = acc[r][2] * invl; o4.w = acc[r][3] * invl;
        *(float4*)(ob + ((size_t)(b * SEQ + sq) * NH + h) * HD + lane * 4) = o4;
    }
}

// ---------------------------------------------------------------------------
extern "C" void kernel_launch(void* const* d_in, const int* in_sizes, int n_in,
                              void* d_out, int out_size) {
    const float* x  = (const float*)d_in[0];
    const float* Wq = (const float*)d_in[1];
    const float* Wk = (const float*)d_in[2];
    const float* Wv = (const float*)d_in[3];
    const float* Wo = (const float*)d_in[4];
    float* out = (float*)d_out;

    float* qbuf; cudaGetSymbolAddress((void**)&qbuf, g_qbuf);
    float* obuf; cudaGetSymbolAddress((void**)&obuf, g_obuf);
    float* kvfb; cudaGetSymbolAddress((void**)&kvfb, g_kvfb);

    const size_t off_k = (size_t)MROWS * HID;
    const size_t off_v = off_k + (size_t)MROWS * HD;
    const size_t need  = off_v + (size_t)MROWS * HD;

    float* kout;
    float* vout;
    if ((size_t)out_size >= need) {
        kout = out + off_k;
        vout = out + off_v;
    } else {
        kout = kvfb;
        vout = kvfb + (size_t)MROWS * HD;
    }

    // unconditional every call — no static guards (determinism contract)
    cudaFuncSetAttribute(flash_kernel, cudaFuncAttributeMaxDynamicSharedMemorySize, FLASH_SMEM);
    cudaFuncSetAttribute(tf32_gemm,    cudaFuncAttributeMaxDynamicSharedMemorySize, GEMM_SMEM);
    cudaFuncSetAttribute(tf32_gemm_kv, cudaFuncAttributeMaxDynamicSharedMemorySize, GEMM_SMEM);

    dim3 gbig(HID / 128, MROWS / 128);      // (16, 32)
    dim3 gkv (1, MROWS / 128, 2);           // (1, 32, 2)

    tf32_gemm   <<<gbig, 256, GEMM_SMEM>>>(x, Wq, qbuf, HID, HID);
    tf32_gemm_kv<<<gkv,  256, GEMM_SMEM>>>(x, Wk, Wv, kout, vout, HID);

    rope_q_kernel<<<dim3(MROWS, NH), 64>>>(qbuf);
    rope_k_kernel<<<MROWS, 64>>>(kout);

    flash_kernel<<<dim3(SEQ / TQ, NH, NB), 128, FLASH_SMEM>>>(qbuf, kout, vout, obuf);

    tf32_gemm<<<gbig, 256, GEMM_SMEM>>>(obuf, Wo, out, HID, HID);
}

// round 5
// speedup vs baseline: 2.9840x; 1.8478x over previous
#include <cuda_runtime.h>
#include <cuda_fp16.h>
#include <math.h>
#include <stdint.h>

#define NB   2
#define SEQ  2048
#define HID  2048
#define NH   16
#define HD   128
#define MROWS (NB*SEQ)   /* 4096 */

// scratch (allocation-free: device globals)
__device__ float g_qbuf[(size_t)MROWS * HID];   // q after proj+rope, [b,s,h,d]
__device__ float g_obuf[(size_t)MROWS * HID];   // attention out, [b,s,h,d]
__device__ float g_kvfb[(size_t)2 * MROWS * HD];

// ===========================================================================
// TF32 tensor-core GEMM NT (unchanged from R4, validated)
// ===========================================================================
#define GPAD 36
#define STAGE_FLOATS (2 * 128 * GPAD)
#define GEMM_SMEM (2 * STAGE_FLOATS * 4)

__device__ __forceinline__ uint32_t f2tf32(float x) {
    uint32_t r;
    asm("cvt.rna.tf32.f32 %0, %1;" : "=r"(r) : "f"(x));
    return r;
}
__device__ __forceinline__ void cp_async16(uint32_t s, const void* g) {
    asm volatile("cp.async.cg.shared.global [%0], [%1], 16;\n" :: "r"(s), "l"(g));
}

__device__ __forceinline__ void gemm_body(const float* __restrict__ A,
                                          const float* __restrict__ Bw,
                                          float* __restrict__ C,
                                          int N, int K, int bm, int bn) {
    extern __shared__ float sm[];
    const int tid  = threadIdx.x;
    const int wid  = tid >> 5, lane = tid & 31;
    const int g    = lane >> 2, t = lane & 3;
    const int wm   = (wid & 3) * 32;
    const int wn   = (wid >> 2) * 64;

    const float* Ab = A  + (size_t)bm * 128 * K;
    const float* Bb = Bw + (size_t)bn * 128 * K;

    float acc[2][8][4];
#pragma unroll
    for (int mt = 0; mt < 2; mt++)
#pragma unroll
        for (int nt = 0; nt < 8; nt++)
#pragma unroll
            for (int c = 0; c < 4; c++) acc[mt][nt][c] = 0.f;

    const uint32_t smb = (uint32_t)__cvta_generic_to_shared(sm);
    const int NKI = K >> 5;

    {
        uint32_t As_s = smb, Bs_s = smb + 128 * GPAD * 4;
#pragma unroll
        for (int i = 0; i < 4; i++) {
            int e = tid + i * 256, row = e >> 3, c4 = (e & 7) * 4;
            cp_async16(As_s + (row * GPAD + c4) * 4, Ab + (size_t)row * K + c4);
            cp_async16(Bs_s + (row * GPAD + c4) * 4, Bb + (size_t)row * K + c4);
        }
        asm volatile("cp.async.commit_group;\n");
    }

    for (int ki = 0; ki < NKI; ki++) {
        if (ki + 1 < NKI) {
            int s = (ki + 1) & 1;
            uint32_t As_s = smb + s * STAGE_FLOATS * 4;
            uint32_t Bs_s = As_s + 128 * GPAD * 4;
            const float* Ag = Ab + (ki + 1) * 32;
            const float* Bg = Bb + (ki + 1) * 32;
#pragma unroll
            for (int i = 0; i < 4; i++) {
                int e = tid + i * 256, row = e >> 3, c4 = (e & 7) * 4;
                cp_async16(As_s + (row * GPAD + c4) * 4, Ag + (size_t)row * K + c4);
                cp_async16(Bs_s + (row * GPAD + c4) * 4, Bg + (size_t)row * K + c4);
            }
            asm volatile("cp.async.commit_group;\n");
            asm volatile("cp.async.wait_group 1;\n");
        } else {
            asm volatile("cp.async.wait_group 0;\n");
        }
        __syncthreads();

        const float* As = sm + (ki & 1) * STAGE_FLOATS;
        const float* Bs = As + 128 * GPAD;

#pragma unroll
        for (int kk = 0; kk < 4; kk++) {
            uint32_t a[2][4], b[8][2];
            const int k = kk * 8 + t;
#pragma unroll
            for (int mt = 0; mt < 2; mt++) {
                int r = wm + mt * 16 + g;
                a[mt][0] = f2tf32(As[r * GPAD + k]);
                a[mt][1] = f2tf32(As[(r + 8) * GPAD + k]);
                a[mt][2] = f2tf32(As[r * GPAD + k + 4]);
                a[mt][3] = f2tf32(As[(r + 8) * GPAD + k + 4]);
            }
#pragma unroll
            for (int nt = 0; nt < 8; nt++) {
                int n = wn + nt * 8 + g;
                b[nt][0] = f2tf32(Bs[n * GPAD + k]);
                b[nt][1] = f2tf32(Bs[n * GPAD + k + 4]);
            }
#pragma unroll
            for (int mt = 0; mt < 2; mt++)
#pragma unroll
                for (int nt = 0; nt < 8; nt++) {
                    asm volatile(
                        "mma.sync.aligned.m16n8k8.row.col.f32.tf32.tf32.f32 "
                        "{%0,%1,%2,%3}, {%4,%5,%6,%7}, {%8,%9}, {%0,%1,%2,%3};\n"
                        : "+f"(acc[mt][nt][0]), "+f"(acc[mt][nt][1]),
                          "+f"(acc[mt][nt][2]), "+f"(acc[mt][nt][3])
                        : "r"(a[mt][0]), "r"(a[mt][1]), "r"(a[mt][2]), "r"(a[mt][3]),
                          "r"(b[nt][0]), "r"(b[nt][1]));
                }
        }
        __syncthreads();
    }

#pragma unroll
    for (int mt = 0; mt < 2; mt++) {
        int r0 = bm * 128 + wm + mt * 16 + g;
#pragma unroll
        for (int nt = 0; nt < 8; nt++) {
            int c0 = bn * 128 + wn + nt * 8 + t * 2;
            float2 v0 = make_float2(acc[mt][nt][0], acc[mt][nt][1]);
            float2 v1 = make_float2(acc[mt][nt][2], acc[mt][nt][3]);
            *(float2*)(C + (size_t)r0 * N + c0)       = v0;
            *(float2*)(C + (size_t)(r0 + 8) * N + c0) = v1;
        }
    }
}

__global__ __launch_bounds__(256) void tf32_gemm(const float* __restrict__ A,
                                                 const float* __restrict__ B,
                                                 float* __restrict__ C,
                                                 int N, int K) {
    gemm_body(A, B, C, N, K, blockIdx.y, blockIdx.x);
}

__global__ __launch_bounds__(256) void tf32_gemm_kv(const float* __restrict__ A,
                                                    const float* __restrict__ Bk,
                                                    const float* __restrict__ Bv,
                                                    float* __restrict__ Ck,
                                                    float* __restrict__ Cv,
                                                    int K) {
    if (blockIdx.z == 0) gemm_body(A, Bk, Ck, HD, K, blockIdx.y, 0);
    else                 gemm_body(A, Bv, Cv, HD, K, blockIdx.y, 0);
}

// ---------------------------------------------------------------------------
// RoPE (unchanged)
// ---------------------------------------------------------------------------
#define LOG2_10000_DIV64 0.20762050593f
#define QSCALE 0.08838834765f

__global__ void rope_q_kernel(float* __restrict__ q) {
    const int bs = blockIdx.x;
    const int h  = blockIdx.y;
    const int j  = threadIdx.x;
    const int s  = bs & (SEQ - 1);
    float inv = exp2f(-(float)j * LOG2_10000_DIV64);
    float sn, cs;
    sincosf((float)s * inv, &sn, &cs);
    float* row = q + ((size_t)bs * NH + h) * HD;
    float x1 = row[j], x2 = row[j + 64];
    row[j]      = (x1 * cs - x2 * sn) * QSCALE;
    row[j + 64] = (x2 * cs + x1 * sn) * QSCALE;
}

__global__ void rope_k_kernel(float* __restrict__ k) {
    const int bs = blockIdx.x;
    const int j  = threadIdx.x;
    const int s  = bs & (SEQ - 1);
    float inv = exp2f(-(float)j * LOG2_10000_DIV64);
    float sn, cs;
    sincosf((float)s * inv, &sn, &cs);
    float* row = k + (size_t)bs * HD;
    float x1 = row[j], x2 = row[j + 64];
    row[j]      = x1 * cs - x2 * sn;
    row[j + 64] = x2 * cs + x1 * sn;
}

// ===========================================================================
// fp16 tensor-core flash attention (fp32 softmax + fp32 accumulation)
// 64 q-rows/CTA, 4 warps (m16 each), key tiles of 32.
// K smem [n=key][k=d] (B operand for S); V smem transposed [n=d][k=key]
// (B operand for AV). Q fragments in registers. P stays in registers:
// S C-fragments map lane-identically onto AV A-fragments.
// ===========================================================================
#define FTQ 64
#define FTK 32
#define NKT (SEQ / FTK)          /* 64 key tiles */
#define KROW 68                  /* K smem row stride, uint32 units (64+4)  */
#define VROW 20                  /* V^T smem row stride, uint32 units (16+4)*/

__device__ __forceinline__ uint32_t pack_h2(float lo, float hi) {
    uint32_t r;
    asm("cvt.rn.f16x2.f32 %0, %1, %2;" : "=r"(r) : "f"(hi), "f"(lo));
    return r;
}

__global__ __launch_bounds__(128) void flash_fp16(const float* __restrict__ qb,
                                                  const float* __restrict__ kb,
                                                  const float* __restrict__ vb,
                                                  float* __restrict__ ob) {
    __shared__ uint32_t Ks[FTK * KROW];   // halves [32][136]
    __shared__ uint32_t Vs[HD * VROW];    // halves [128][40]

    const int b = blockIdx.z, h = blockIdx.y, qt = blockIdx.x;
    const int tid = threadIdx.x, w = tid >> 5, lane = tid & 31;
    const int g = lane >> 2, t = lane & 3;

    // ---- Q fragments (rows r0 = qt*64 + w*16 + g, r1 = r0+8), fp16-packed
    uint32_t qf[8][4];
    {
        const float* Q0 = qb + ((size_t)(b * SEQ + qt * FTQ + w * 16 + g) * NH + h) * HD;
        const float* Q1 = Q0 + (size_t)8 * NH * HD;
#pragma unroll
        for (int ks = 0; ks < 8; ks++) {
            float2 x0 = *(const float2*)(Q0 + ks * 16 + 2 * t);
            float2 x1 = *(const float2*)(Q1 + ks * 16 + 2 * t);
            float2 x2 = *(const float2*)(Q0 + ks * 16 + 2 * t + 8);
            float2 x3 = *(const float2*)(Q1 + ks * 16 + 2 * t + 8);
            qf[ks][0] = pack_h2(x0.x, x0.y);
            qf[ks][1] = pack_h2(x1.x, x1.y);
            qf[ks][2] = pack_h2(x2.x, x2.y);
            qf[ks][3] = pack_h2(x3.x, x3.y);
        }
    }

    float acc[16][4];
#pragma unroll
    for (int nt = 0; nt < 16; nt++)
#pragma unroll
        for (int c = 0; c < 4; c++) acc[nt][c] = 0.f;
    float m0 = -1e30f, m1 = -1e30f, l0 = 0.f, l1 = 0.f;

    const int jrow = tid >> 2;           // 0..31: K/V source row
    const int qd   = (tid & 3) * 32;     // 0,32,64,96: d-quarter

    for (int it = 0; it < NKT; it++) {
        if (it) __syncthreads();
        // ---- load K tile [32 x 128] -> Ks[n][k] halves (coalesced float4)
        {
            const float* Kg = kb + (size_t)(b * SEQ + it * FTK + jrow) * HD + qd;
            uint32_t* Kd = Ks + jrow * KROW + (qd >> 1);
#pragma unroll
            for (int i = 0; i < 8; i++) {
                float4 v = *(const float4*)(Kg + i * 4);
                Kd[i * 2 + 0] = pack_h2(v.x, v.y);
                Kd[i * 2 + 1] = pack_h2(v.z, v.w);
            }
            // ---- load V tile and transpose -> Vs[d][j] halves
            const float* Vg = vb + (size_t)(b * SEQ + it * FTK + jrow) * HD + qd;
            __half* Vh = (__half*)Vs;
#pragma unroll
            for (int i = 0; i < 8; i++) {
                float4 v = *(const float4*)(Vg + i * 4);
                Vh[(qd + i * 4 + 0) * (2 * VROW) + jrow] = __float2half(v.x);
                Vh[(qd + i * 4 + 1) * (2 * VROW) + jrow] = __float2half(v.y);
                Vh[(qd + i * 4 + 2) * (2 * VROW) + jrow] = __float2half(v.z);
                Vh[(qd + i * 4 + 3) * (2 * VROW) + jrow] = __float2half(v.w);
            }
        }
        __syncthreads();

        // ---- S = Q K^T  (m16 x n32, k=128 in 8 k16 steps)
        float sacc[4][4];
#pragma unroll
        for (int nt = 0; nt < 4; nt++)
#pragma unroll
            for (int c = 0; c < 4; c++) sacc[nt][c] = 0.f;

#pragma unroll
        for (int ks = 0; ks < 8; ks++) {
#pragma unroll
            for (int nt = 0; nt < 4; nt++) {
                uint32_t b0 = Ks[(nt * 8 + g) * KROW + ks * 8 + t];
                uint32_t b1 = Ks[(nt * 8 + g) * KROW + ks * 8 + t + 4];
                asm volatile(
                    "mma.sync.aligned.m16n8k16.row.col.f32.f16.f16.f32 "
                    "{%0,%1,%2,%3}, {%4,%5,%6,%7}, {%8,%9}, {%0,%1,%2,%3};\n"
                    : "+f"(sacc[nt][0]), "+f"(sacc[nt][1]),
                      "+f"(sacc[nt][2]), "+f"(sacc[nt][3])
                    : "r"(qf[ks][0]), "r"(qf[ks][1]), "r"(qf[ks][2]), "r"(qf[ks][3]),
                      "r"(b0), "r"(b1));
            }
        }

        // ---- online softmax (fp32). row g: c0,c1; row g+8: c2,c3
        float mx0 = sacc[0][0], mx1 = sacc[0][2];
#pragma unroll
        for (int nt = 0; nt < 4; nt++) {
            mx0 = fmaxf(mx0, fmaxf(sacc[nt][0], sacc[nt][1]));
            mx1 = fmaxf(mx1, fmaxf(sacc[nt][2], sacc[nt][3]));
        }
        mx0 = fmaxf(mx0, __shfl_xor_sync(0xffffffffu, mx0, 1));
        mx0 = fmaxf(mx0, __shfl_xor_sync(0xffffffffu, mx0, 2));
        mx1 = fmaxf(mx1, __shfl_xor_sync(0xffffffffu, mx1, 1));
        mx1 = fmaxf(mx1, __shfl_xor_sync(0xffffffffu, mx1, 2));

        float mn0 = fmaxf(m0, mx0), mn1 = fmaxf(m1, mx1);
        float sum0 = 0.f, sum1 = 0.f;
#pragma unroll
        for (int nt = 0; nt < 4; nt++) {
            sacc[nt][0] = __expf(sacc[nt][0] - mn0);
            sacc[nt][1] = __expf(sacc[nt][1] - mn0);
            sacc[nt][2] = __expf(sacc[nt][2] - mn1);
            sacc[nt][3] = __expf(sacc[nt][3] - mn1);
            sum0 += sacc[nt][0] + sacc[nt][1];
            sum1 += sacc[nt][2] + sacc[nt][3];
        }
        sum0 += __shfl_xor_sync(0xffffffffu, sum0, 1);
        sum0 += __shfl_xor_sync(0xffffffffu, sum0, 2);
        sum1 += __shfl_xor_sync(0xffffffffu, sum1, 1);
        sum1 += __shfl_xor_sync(0xffffffffu, sum1, 2);

        float c0 = __expf(m0 - mn0), c1 = __expf(m1 - mn1);
        l0 = l0 * c0 + sum0; l1 = l1 * c1 + sum1;
        m0 = mn0; m1 = mn1;
#pragma unroll
        for (int nt = 0; nt < 16; nt++) {
            acc[nt][0] *= c0; acc[nt][1] *= c0;
            acc[nt][2] *= c1; acc[nt][3] *= c1;
        }

        // ---- P fragments (register-only re-pack: S C-frag -> AV A-frag)
        uint32_t pa[2][4];
#pragma unroll
        for (int k2 = 0; k2 < 2; k2++) {
            pa[k2][0] = pack_h2(sacc[2 * k2][0],     sacc[2 * k2][1]);
            pa[k2][1] = pack_h2(sacc[2 * k2][2],     sacc[2 * k2][3]);
            pa[k2][2] = pack_h2(sacc[2 * k2 + 1][0], sacc[2 * k2 + 1][1]);
            pa[k2][3] = pack_h2(sacc[2 * k2 + 1][2], sacc[2 * k2 + 1][3]);
        }

        // ---- O += P V  (m16 x n128, k=32 in 2 k16 steps)
#pragma unroll
        for (int k2 = 0; k2 < 2; k2++) {
#pragma unroll
            for (int nt = 0; nt < 16; nt++) {
                uint32_t b0 = Vs[(nt * 8 + g) * VROW + k2 * 8 + t];
                uint32_t b1 = Vs[(nt * 8 + g) * VROW + k2 * 8 + t + 4];
                asm volatile(
                    "mma.sync.aligned.m16n8k16.row.col.f32.f16.f16.f32 "
                    "{%0,%1,%2,%3}, {%4,%5,%6,%7}, {%8,%9}, {%0,%1,%2,%3};\n"
                    : "+f"(acc[nt][0]), "+f"(acc[nt][1]),
                      "+f"(acc[nt][2]), "+f"(acc[nt][3])
                    : "r"(pa[k2][0]), "r"(pa[k2][1]), "r"(pa[k2][2]), "r"(pa[k2][3]),
                      "r"(b0), "r"(b1));
            }
        }
    }

    // ---- epilogue
    float il0 = 1.f / l0, il1 = 1.f / l1;
    float* O0 = ob + ((size_t)(b * SEQ + qt * FTQ + w * 16 + g) * NH + h) * HD;
    float* O1 = O0 + (size_t)8 * NH * HD;
#pragma unroll
    for (int nt = 0; nt < 16; nt++) {
        *(float2*)(O0 + nt * 8 + 2 * t) = make_float2(acc[nt][0] * il0, acc[nt][1] * il0);
        *(float2*)(O1 + nt * 8 + 2 * t) = make_float2(acc[nt][2] * il1, acc[nt][3] * il1);
    }
}

// ---------------------------------------------------------------------------
extern "C" void kernel_launch(void* const* d_in, const int* in_sizes, int n_in,
                              void* d_out, int out_size) {
    const float* x  = (const float*)d_in[0];
    const float* Wq = (const float*)d_in[1];
    const float* Wk = (const float*)d_in[2];
    const float* Wv = (const float*)d_in[3];
    const float* Wo = (const float*)d_in[4];
    float* out = (float*)d_out;

    float* qbuf; cudaGetSymbolAddress((void**)&qbuf, g_qbuf);
    float* obuf; cudaGetSymbolAddress((void**)&obuf, g_obuf);
    float* kvfb; cudaGetSymbolAddress((void**)&kvfb, g_kvfb);

    const size_t off_k = (size_t)MROWS * HID;
    const size_t off_v = off_k + (size_t)MROWS * HD;
    const size_t need  = off_v + (size_t)MROWS * HD;

    float* kout;
    float* vout;
    if ((size_t)out_size >= need) {
        kout = out + off_k;
        vout = out + off_v;
    } else {
        kout = kvfb;
        vout = kvfb + (size_t)MROWS * HD;
    }

    cudaFuncSetAttribute(tf32_gemm,    cudaFuncAttributeMaxDynamicSharedMemorySize, GEMM_SMEM);
    cudaFuncSetAttribute(tf32_gemm_kv, cudaFuncAttributeMaxDynamicSharedMemorySize, GEMM_SMEM);

    dim3 gbig(HID / 128, MROWS / 128);      // (16, 32)
    dim3 gkv (1, MROWS / 128, 2);           // (1, 32, 2)

    tf32_gemm   <<<gbig, 256, GEMM_SMEM>>>(x, Wq, qbuf, HID, HID);
    tf32_gemm_kv<<<gkv,  256, GEMM_SMEM>>>(x, Wk, Wv, kout, vout, HID);

    rope_q_kernel<<<dim3(MROWS, NH), 64>>>(qbuf);
    rope_k_kernel<<<MROWS, 64>>>(kout);

    flash_fp16<<<dim3(SEQ / FTQ, NH, NB), 128>>>(qbuf, kout, vout, obuf);

    tf32_gemm<<<gbig, 256, GEMM_SMEM>>>(obuf, Wo, out, HID, HID);
}

// round 6
// speedup vs baseline: 3.7135x; 1.2445x over previous
#include <cuda_runtime.h>
#include <cuda_fp16.h>
#include <math.h>
#include <stdint.h>

#define NB   2
#define SEQ  2048
#define HID  2048
#define NH   16
#define HD   128
#define MROWS (NB*SEQ)   /* 4096 */

// scratch (allocation-free: device globals)
__device__ float  g_qbuf[(size_t)MROWS * HID];   // q after proj+rope (fp32)
__device__ float  g_kvfb[(size_t)2 * MROWS * HD];
__device__ __half g_xh [(size_t)MROWS * HID];    // x in fp16
__device__ __half g_wqh[(size_t)HID * HID];      // Wq * QSCALE in fp16
__device__ __half g_wkh[(size_t)HD * HID];
__device__ __half g_wvh[(size_t)HD * HID];
__device__ __half g_woh[(size_t)HID * HID];
__device__ __half g_oh [(size_t)MROWS * HID];    // attention out (fp16)

#define QSCALE 0.08838834765f   /* 1/sqrt(128) */
#define LOG2_10000_DIV64 0.20762050593f

// ---------------------------------------------------------------------------
// fp32 -> fp16 conversion (vectorized, optional scale)
// ---------------------------------------------------------------------------
__global__ void f2h_kernel(const float* __restrict__ in, __half* __restrict__ out,
                           int n4, float scale) {
    int i = blockIdx.x * blockDim.x + threadIdx.x;
    if (i < n4) {
        float4 v = ((const float4*)in)[i];
        ((__half2*)out)[2 * i + 0] = __floats2half2_rn(v.x * scale, v.y * scale);
        ((__half2*)out)[2 * i + 1] = __floats2half2_rn(v.z * scale, v.w * scale);
    }
}

// ===========================================================================
// fp16 tensor-core GEMM NT: C[M,N] = A[M,K] * B[N,K]^T (fp16 in, fp32 out)
// CTA tile 128x128x64(halves), 256 threads = 8 warps (4m x 2n), warp 32x64.
// mma.sync.m16n8k16, cp.async double-buffered, +8 half row pad (bank-clean).
// ===========================================================================
#define HPAD 72                        /* 64 + 8 halves per smem row */
#define STAGEH (2 * 128 * HPAD)        /* A+B halves per stage = 18432 */
#define HGEMM_SMEM (2 * STAGEH * 2)    /* 73728 bytes */

__device__ __forceinline__ void cp_async16(uint32_t s, const void* g) {
    asm volatile("cp.async.cg.shared.global [%0], [%1], 16;\n" :: "r"(s), "l"(g));
}

__device__ __forceinline__ void hgemm_body(const __half* __restrict__ A,
                                           const __half* __restrict__ Bw,
                                           float* __restrict__ C,
                                           int N, int K, int bm, int bn) {
    extern __shared__ __half hsm[];
    const int tid  = threadIdx.x;
    const int wid  = tid >> 5, lane = tid & 31;
    const int g    = lane >> 2, t = lane & 3;
    const int wm   = (wid & 3) * 32;
    const int wn   = (wid >> 2) * 64;

    const __half* Ab = A  + (size_t)bm * 128 * K;
    const __half* Bb = Bw + (size_t)bn * 128 * K;

    float acc[2][8][4];
#pragma unroll
    for (int mt = 0; mt < 2; mt++)
#pragma unroll
        for (int nt = 0; nt < 8; nt++)
#pragma unroll
            for (int c = 0; c < 4; c++) acc[mt][nt][c] = 0.f;

    const uint32_t smb = (uint32_t)__cvta_generic_to_shared(hsm);
    const int NKI = K >> 6;

    // prefetch tile 0: 128 rows x 64 halves (128B) each for A,B = 8 chunks/row
    {
        uint32_t As_s = smb, Bs_s = smb + 128 * HPAD * 2;
#pragma unroll
        for (int i = 0; i < 4; i++) {
            int e = tid + i * 256, row = e >> 3, c = (e & 7) * 8;
            cp_async16(As_s + (row * HPAD + c) * 2, Ab + (size_t)row * K + c);
            cp_async16(Bs_s + (row * HPAD + c) * 2, Bb + (size_t)row * K + c);
        }
        asm volatile("cp.async.commit_group;\n");
    }

    for (int ki = 0; ki < NKI; ki++) {
        if (ki + 1 < NKI) {
            int s = (ki + 1) & 1;
            uint32_t As_s = smb + s * STAGEH * 2;
            uint32_t Bs_s = As_s + 128 * HPAD * 2;
            const __half* Ag = Ab + (ki + 1) * 64;
            const __half* Bg = Bb + (ki + 1) * 64;
#pragma unroll
            for (int i = 0; i < 4; i++) {
                int e = tid + i * 256, row = e >> 3, c = (e & 7) * 8;
                cp_async16(As_s + (row * HPAD + c) * 2, Ag + (size_t)row * K + c);
                cp_async16(Bs_s + (row * HPAD + c) * 2, Bg + (size_t)row * K + c);
            }
            asm volatile("cp.async.commit_group;\n");
            asm volatile("cp.async.wait_group 1;\n");
        } else {
            asm volatile("cp.async.wait_group 0;\n");
        }
        __syncthreads();

        const __half* As = hsm + (ki & 1) * STAGEH;
        const __half* Bs = As + 128 * HPAD;

#pragma unroll
        for (int ks = 0; ks < 4; ks++) {
            uint32_t a[2][4], b[8][2];
            const int k = ks * 16 + 2 * t;
#pragma unroll
            for (int mt = 0; mt < 2; mt++) {
                int r = wm + mt * 16 + g;
                a[mt][0] = *(const uint32_t*)(As + r * HPAD + k);
                a[mt][1] = *(const uint32_t*)(As + (r + 8) * HPAD + k);
                a[mt][2] = *(const uint32_t*)(As + r * HPAD + k + 8);
                a[mt][3] = *(const uint32_t*)(As + (r + 8) * HPAD + k + 8);
            }
#pragma unroll
            for (int nt = 0; nt < 8; nt++) {
                int n = wn + nt * 8 + g;
                b[nt][0] = *(const uint32_t*)(Bs + n * HPAD + k);
                b[nt][1] = *(const uint32_t*)(Bs + n * HPAD + k + 8);
            }
#pragma unroll
            for (int mt = 0; mt < 2; mt++)
#pragma unroll
                for (int nt = 0; nt < 8; nt++) {
                    asm volatile(
                        "mma.sync.aligned.m16n8k16.row.col.f32.f16.f16.f32 "
                        "{%0,%1,%2,%3}, {%4,%5,%6,%7}, {%8,%9}, {%0,%1,%2,%3};\n"
                        : "+f"(acc[mt][nt][0]), "+f"(acc[mt][nt][1]),
                          "+f"(acc[mt][nt][2]), "+f"(acc[mt][nt][3])
                        : "r"(a[mt][0]), "r"(a[mt][1]), "r"(a[mt][2]), "r"(a[mt][3]),
                          "r"(b[nt][0]), "r"(b[nt][1]));
                }
        }
        __syncthreads();
    }

    // epilogue: c0:(g,2t) c1:(g,2t+1) c2:(g+8,2t) c3:(g+8,2t+1)
#pragma unroll
    for (int mt = 0; mt < 2; mt++) {
        int r0 = bm * 128 + wm + mt * 16 + g;
#pragma unroll
        for (int nt = 0; nt < 8; nt++) {
            int c0 = bn * 128 + wn + nt * 8 + t * 2;
            *(float2*)(C + (size_t)r0 * N + c0)       = make_float2(acc[mt][nt][0], acc[mt][nt][1]);
            *(float2*)(C + (size_t)(r0 + 8) * N + c0) = make_float2(acc[mt][nt][2], acc[mt][nt][3]);
        }
    }
}

__global__ __launch_bounds__(256) void hgemm(const __half* __restrict__ A,
                                             const __half* __restrict__ B,
                                             float* __restrict__ C,
                                             int N, int K) {
    hgemm_body(A, B, C, N, K, blockIdx.y, blockIdx.x);
}

__global__ __launch_bounds__(256) void hgemm_kv(const __half* __restrict__ A,
                                                const __half* __restrict__ Bk,
                                                const __half* __restrict__ Bv,
                                                float* __restrict__ Ck,
                                                float* __restrict__ Cv,
                                                int K) {
    if (blockIdx.z == 0) hgemm_body(A, Bk, Ck, HD, K, blockIdx.y, 0);
    else                 hgemm_body(A, Bv, Cv, HD, K, blockIdx.y, 0);
}

// ---------------------------------------------------------------------------
// RoPE (QSCALE folded into Wq conversion; rope_q is now pure rotation)
// ---------------------------------------------------------------------------
__global__ void rope_q_kernel(float* __restrict__ q) {
    const int bs = blockIdx.x;
    const int h  = blockIdx.y;
    const int j  = threadIdx.x;
    const int s  = bs & (SEQ - 1);
    float inv = exp2f(-(float)j * LOG2_10000_DIV64);
    float sn, cs;
    sincosf((float)s * inv, &sn, &cs);
    float* row = q + ((size_t)bs * NH + h) * HD;
    float x1 = row[j], x2 = row[j + 64];
    row[j]      = x1 * cs - x2 * sn;
    row[j + 64] = x2 * cs + x1 * sn;
}

__global__ void rope_k_kernel(float* __restrict__ k) {
    const int bs = blockIdx.x;
    const int j  = threadIdx.x;
    const int s  = bs & (SEQ - 1);
    float inv = exp2f(-(float)j * LOG2_10000_DIV64);
    float sn, cs;
    sincosf((float)s * inv, &sn, &cs);
    float* row = k + (size_t)bs * HD;
    float x1 = row[j], x2 = row[j + 64];
    row[j]      = x1 * cs - x2 * sn;
    row[j + 64] = x2 * cs + x1 * sn;
}

// ===========================================================================
// fp16 tensor-core flash attention (fp32 softmax + fp32 accum) — validated R5.
// Output now written directly as fp16 (feeds O-proj A operand).
// ===========================================================================
#define FTQ 64
#define FTK 32
#define NKT (SEQ / FTK)
#define KROW 68
#define VROW 20

__device__ __forceinline__ uint32_t pack_h2(float lo, float hi) {
    uint32_t r;
    asm("cvt.rn.f16x2.f32 %0, %1, %2;" : "=r"(r) : "f"(hi), "f"(lo));
    return r;
}

__global__ __launch_bounds__(128) void flash_fp16(const float* __restrict__ qb,
                                                  const float* __restrict__ kb,
                                                  const float* __restrict__ vb,
                                                  __half* __restrict__ ob) {
    __shared__ uint32_t Ks[FTK * KROW];
    __shared__ uint32_t Vs[HD * VROW];

    const int b = blockIdx.z, h = blockIdx.y, qt = blockIdx.x;
    const int tid = threadIdx.x, w = tid >> 5, lane = tid & 31;
    const int g = lane >> 2, t = lane & 3;

    uint32_t qf[8][4];
    {
        const float* Q0 = qb + ((size_t)(b * SEQ + qt * FTQ + w * 16 + g) * NH + h) * HD;
        const float* Q1 = Q0 + (size_t)8 * NH * HD;
#pragma unroll
        for (int ks = 0; ks < 8; ks++) {
            float2 x0 = *(const float2*)(Q0 + ks * 16 + 2 * t);
            float2 x1 = *(const float2*)(Q1 + ks * 16 + 2 * t);
            float2 x2 = *(const float2*)(Q0 + ks * 16 + 2 * t + 8);
            float2 x3 = *(const float2*)(Q1 + ks * 16 + 2 * t + 8);
            qf[ks][0] = pack_h2(x0.x, x0.y);
            qf[ks][1] = pack_h2(x1.x, x1.y);
            qf[ks][2] = pack_h2(x2.x, x2.y);
            qf[ks][3] = pack_h2(x3.x, x3.y);
        }
    }

    float acc[16][4];
#pragma unroll
    for (int nt = 0; nt < 16; nt++)
#pragma unroll
        for (int c = 0; c < 4; c++) acc[nt][c] = 0.f;
    float m0 = -1e30f, m1 = -1e30f, l0 = 0.f, l1 = 0.f;

    const int jrow = tid >> 2;
    const int qd   = (tid & 3) * 32;

    for (int it = 0; it < NKT; it++) {
        if (it) __syncthreads();
        {
            const float* Kg = kb + (size_t)(b * SEQ + it * FTK + jrow) * HD + qd;
            uint32_t* Kd = Ks + jrow * KROW + (qd >> 1);
#pragma unroll
            for (int i = 0; i < 8; i++) {
                float4 v = *(const float4*)(Kg + i * 4);
                Kd[i * 2 + 0] = pack_h2(v.x, v.y);
                Kd[i * 2 + 1] = pack_h2(v.z, v.w);
            }
            const float* Vg = vb + (size_t)(b * SEQ + it * FTK + jrow) * HD + qd;
            __half* Vh = (__half*)Vs;
#pragma unroll
            for (int i = 0; i < 8; i++) {
                float4 v = *(const float4*)(Vg + i * 4);
                Vh[(qd + i * 4 + 0) * (2 * VROW) + jrow] = __float2half(v.x);
                Vh[(qd + i * 4 + 1) * (2 * VROW) + jrow] = __float2half(v.y);
                Vh[(qd + i * 4 + 2) * (2 * VROW) + jrow] = __float2half(v.z);
                Vh[(qd + i * 4 + 3) * (2 * VROW) + jrow] = __float2half(v.w);
            }
        }
        __syncthreads();

        float sacc[4][4];
#pragma unroll
        for (int nt = 0; nt < 4; nt++)
#pragma unroll
            for (int c = 0; c < 4; c++) sacc[nt][c] = 0.f;

#pragma unroll
        for (int ks = 0; ks < 8; ks++) {
#pragma unroll
            for (int nt = 0; nt < 4; nt++) {
                uint32_t b0 = Ks[(nt * 8 + g) * KROW + ks * 8 + t];
                uint32_t b1 = Ks[(nt * 8 + g) * KROW + ks * 8 + t + 4];
                asm volatile(
                    "mma.sync.aligned.m16n8k16.row.col.f32.f16.f16.f32 "
                    "{%0,%1,%2,%3}, {%4,%5,%6,%7}, {%8,%9}, {%0,%1,%2,%3};\n"
                    : "+f"(sacc[nt][0]), "+f"(sacc[nt][1]),
                      "+f"(sacc[nt][2]), "+f"(sacc[nt][3])
                    : "r"(qf[ks][0]), "r"(qf[ks][1]), "r"(qf[ks][2]), "r"(qf[ks][3]),
                      "r"(b0), "r"(b1));
            }
        }

        float mx0 = sacc[0][0], mx1 = sacc[0][2];
#pragma unroll
        for (int nt = 0; nt < 4; nt++) {
            mx0 = fmaxf(mx0, fmaxf(sacc[nt][0], sacc[nt][1]));
            mx1 = fmaxf(mx1, fmaxf(sacc[nt][2], sacc[nt][3]));
        }
        mx0 = fmaxf(mx0, __shfl_xor_sync(0xffffffffu, mx0, 1));
        mx0 = fmaxf(mx0, __shfl_xor_sync(0xffffffffu, mx0, 2));
        mx1 = fmaxf(mx1, __shfl_xor_sync(0xffffffffu, mx1, 1));
        mx1 = fmaxf(mx1, __shfl_xor_sync(0xffffffffu, mx1, 2));

        float mn0 = fmaxf(m0, mx0), mn1 = fmaxf(m1, mx1);
        float sum0 = 0.f, sum1 = 0.f;
#pragma unroll
        for (int nt = 0; nt < 4; nt++) {
            sacc[nt][0] = __expf(sacc[nt][0] - mn0);
            sacc[nt][1] = __expf(sacc[nt][1] - mn0);
            sacc[nt][2] = __expf(sacc[nt][2] - mn1);
            sacc[nt][3] = __expf(sacc[nt][3] - mn1);
            sum0 += sacc[nt][0] + sacc[nt][1];
            sum1 += sacc[nt][2] + sacc[nt][3];
        }
        sum0 += __shfl_xor_sync(0xffffffffu, sum0, 1);
        sum0 += __shfl_xor_sync(0xffffffffu, sum0, 2);
        sum1 += __shfl_xor_sync(0xffffffffu, sum1, 1);
        sum1 += __shfl_xor_sync(0xffffffffu, sum1, 2);

        float c0 = __expf(m0 - mn0), c1 = __expf(m1 - mn1);
        l0 = l0 * c0 + sum0; l1 = l1 * c1 + sum1;
        m0 = mn0; m1 = mn1;
#pragma unroll
        for (int nt = 0; nt < 16; nt++) {
            acc[nt][0] *= c0; acc[nt][1] *= c0;
            acc[nt][2] *= c1; acc[nt][3] *= c1;
        }

        uint32_t pa[2][4];
#pragma unroll
        for (int k2 = 0; k2 < 2; k2++) {
            pa[k2][0] = pack_h2(sacc[2 * k2][0],     sacc[2 * k2][1]);
            pa[k2][1] = pack_h2(sacc[2 * k2][2],     sacc[2 * k2][3]);
            pa[k2][2] = pack_h2(sacc[2 * k2 + 1][0], sacc[2 * k2 + 1][1]);
            pa[k2][3] = pack_h2(sacc[2 * k2 + 1][2], sacc[2 * k2 + 1][3]);
        }

#pragma unroll
        for (int k2 = 0; k2 < 2; k2++) {
#pragma unroll
            for (int nt = 0; nt < 16; nt++) {
                uint32_t b0 = Vs[(nt * 8 + g) * VROW + k2 * 8 + t];
                uint32_t b1 = Vs[(nt * 8 + g) * VROW + k2 * 8 + t + 4];
                asm volatile(
                    "mma.sync.aligned.m16n8k16.row.col.f32.f16.f16.f32 "
                    "{%0,%1,%2,%3}, {%4,%5,%6,%7}, {%8,%9}, {%0,%1,%2,%3};\n"
                    : "+f"(acc[nt][0]), "+f"(acc[nt][1]),
                      "+f"(acc[nt][2]), "+f"(acc[nt][3])
                    : "r"(pa[k2][0]), "r"(pa[k2][1]), "r"(pa[k2][2]), "r"(pa[k2][3]),
                      "r"(b0), "r"(b1));
            }
        }
    }

    float il0 = 1.f / l0, il1 = 1.f / l1;
    __half* O0 = ob + ((size_t)(b * SEQ + qt * FTQ + w * 16 + g) * NH + h) * HD;
    __half* O1 = O0 + (size_t)8 * NH * HD;
#pragma unroll
    for (int nt = 0; nt < 16; nt++) {
        *(__half2*)(O0 + nt * 8 + 2 * t) = __floats2half2_rn(acc[nt][0] * il0, acc[nt][1] * il0);
        *(__half2*)(O1 + nt * 8 + 2 * t) = __floats2half2_rn(acc[nt][2] * il1, acc[nt][3] * il1);
    }
}

// ---------------------------------------------------------------------------
extern "C" void kernel_launch(void* const* d_in, const int* in_sizes, int n_in,
                              void* d_out, int out_size) {
    const float* x  = (const float*)d_in[0];
    const float* Wq = (const float*)d_in[1];
    const float* Wk = (const float*)d_in[2];
    const float* Wv = (const float*)d_in[3];
    const float* Wo = (const float*)d_in[4];
    float* out = (float*)d_out;

    float*  qbuf; cudaGetSymbolAddress((void**)&qbuf, g_qbuf);
    float*  kvfb; cudaGetSymbolAddress((void**)&kvfb, g_kvfb);
    __half* xh;   cudaGetSymbolAddress((void**)&xh,  g_xh);
    __half* wqh;  cudaGetSymbolAddress((void**)&wqh, g_wqh);
    __half* wkh;  cudaGetSymbolAddress((void**)&wkh, g_wkh);
    __half* wvh;  cudaGetSymbolAddress((void**)&wvh, g_wvh);
    __half* woh;  cudaGetSymbolAddress((void**)&woh, g_woh);
    __half* oh;   cudaGetSymbolAddress((void**)&oh,  g_oh);

    const size_t off_k = (size_t)MROWS * HID;
    const size_t off_v = off_k + (size_t)MROWS * HD;
    const size_t need  = off_v + (size_t)MROWS * HD;

    float* kout;
    float* vout;
    if ((size_t)out_size >= need) {
        kout = out + off_k;
        vout = out + off_v;
    } else {
        kout = kvfb;
        vout = kvfb + (size_t)MROWS * HD;
    }

    cudaFuncSetAttribute(hgemm,    cudaFuncAttributeMaxDynamicSharedMemorySize, HGEMM_SMEM);
    cudaFuncSetAttribute(hgemm_kv, cudaFuncAttributeMaxDynamicSharedMemorySize, HGEMM_SMEM);

    // fp32 -> fp16 conversions (x and weights; QSCALE folded into Wq)
    f2h_kernel<<<(MROWS * HID / 4 + 255) / 256, 256>>>(x,  xh,  MROWS * HID / 4, 1.f);
    f2h_kernel<<<(HID * HID / 4 + 255) / 256, 256>>>(Wq, wqh, HID * HID / 4, QSCALE);
    f2h_kernel<<<(HD * HID / 4 + 255) / 256, 256>>>(Wk, wkh, HD * HID / 4, 1.f);
    f2h_kernel<<<(HD * HID / 4 + 255) / 256, 256>>>(Wv, wvh, HD * HID / 4, 1.f);
    f2h_kernel<<<(HID * HID / 4 + 255) / 256, 256>>>(Wo, woh, HID * HID / 4, 1.f);

    dim3 gbig(HID / 128, MROWS / 128);      // (16, 32)
    dim3 gkv (1, MROWS / 128, 2);           // (1, 32, 2)

    hgemm   <<<gbig, 256, HGEMM_SMEM>>>(xh, wqh, qbuf, HID, HID);
    hgemm_kv<<<gkv,  256, HGEMM_SMEM>>>(xh, wkh, wvh, kout, vout, HID);

    rope_q_kernel<<<dim3(MROWS, NH), 64>>>(qbuf);
    rope_k_kernel<<<MROWS, 64>>>(kout);

    flash_fp16<<<dim3(SEQ / FTQ, NH, NB), 128>>>(qbuf, kout, vout, oh);

    hgemm<<<gbig, 256, HGEMM_SMEM>>>(oh, woh, out, HID, HID);
}

// round 10
// speedup vs baseline: 3.8284x; 1.0309x over previous
#include <cuda_runtime.h>
#include <cuda_fp16.h>
#include <math.h>
#include <stdint.h>

#define NB   2
#define SEQ  2048
#define HID  2048
#define NH   16
#define HD   128
#define MROWS (NB*SEQ)   /* 4096 */

// scratch (allocation-free: device globals)
__device__ float  g_qbuf[(size_t)MROWS * HID];
__device__ float  g_kvfb[(size_t)2 * MROWS * HD];
__device__ __half g_xh [(size_t)MROWS * HID];
__device__ __half g_wqh[(size_t)HID * HID];      // Wq * QSCALE
__device__ __half g_wkh[(size_t)HD * HID];
__device__ __half g_wvh[(size_t)HD * HID];
__device__ __half g_woh[(size_t)HID * HID];
__device__ __half g_oh [(size_t)MROWS * HID];

#define QSCALE 0.08838834765f
#define LOG2_10000_DIV64 0.20762050593f

// ---------------------------------------------------------------------------
__global__ void f2h_kernel(const float* __restrict__ in, __half* __restrict__ out,
                           int n4, float scale) {
    int i = blockIdx.x * blockDim.x + threadIdx.x;
    if (i < n4) {
        float4 v = ((const float4*)in)[i];
        ((__half2*)out)[2 * i + 0] = __floats2half2_rn(v.x * scale, v.y * scale);
        ((__half2*)out)[2 * i + 1] = __floats2half2_rn(v.z * scale, v.w * scale);
    }
}

// ===========================================================================
// fp16 mma.sync GEMM NT with ldmatrix fragments + 3-stage cp.async pipeline.
// C[M,N] = A[M,K] * B[N,K]^T.  CTA tile 128x128, chunk = 64 halves.
// 256 threads = 8 warps (4m x 2n), warp tile 32x64.
// ===========================================================================
#define HPAD 72                         /* 64 + 8 halves per smem row */
#define HSTAGE (2 * 128 * HPAD)         /* halves per stage (A+B) = 18432 */
#define HG_NSTAGE 3
#define HG_SMEM (HG_NSTAGE * HSTAGE * 2)   /* 110592 bytes */

__device__ __forceinline__ void cp_async16(uint32_t s, const void* g) {
    asm volatile("cp.async.cg.shared.global [%0], [%1], 16;\n" :: "r"(s), "l"(g));
}
__device__ __forceinline__ void ldsm_x4(uint32_t& r0, uint32_t& r1,
                                        uint32_t& r2, uint32_t& r3, uint32_t a) {
    asm volatile("ldmatrix.sync.aligned.m8n8.x4.shared.b16 {%0,%1,%2,%3}, [%4];"
                 : "=r"(r0), "=r"(r1), "=r"(r2), "=r"(r3) : "r"(a));
}

__device__ __forceinline__ void hgemm_body(const __half* __restrict__ A,
                                           const __half* __restrict__ Bw,
                                           float* __restrict__ C,
                                           int N, int K, int bm, int bn) {
    extern __shared__ __half hsm[];
    const int tid  = threadIdx.x;
    const int wid  = tid >> 5, lane = tid & 31;
    const int g    = lane >> 2, t = lane & 3;
    const int wm   = (wid & 3) * 32;
    const int wn   = (wid >> 2) * 64;

    const __half* Ab = A  + (size_t)bm * 128 * K;
    const __half* Bb = Bw + (size_t)bn * 128 * K;
    const int NC = K >> 6;

    float acc[2][8][4];
#pragma unroll
    for (int mt = 0; mt < 2; mt++)
#pragma unroll
        for (int nt = 0; nt < 8; nt++)
#pragma unroll
            for (int c = 0; c < 4; c++) acc[mt][nt][c] = 0.f;

    const uint32_t smb = (uint32_t)__cvta_generic_to_shared(hsm);
    const int lrow = tid >> 3, lcg = (tid & 7) * 8;   /* loader: row, col(halves) */

    // ldmatrix lane addressing (within-stage offsets, halves)
    const int a_row = (lane & 15), a_col = (lane >> 4) << 3;
    const int b_row = ((lane >> 4) << 3) + (lane & 7), b_col = ((lane >> 3) & 1) << 3;

    // prologue: prefetch chunks 0,1
#pragma unroll
    for (int c = 0; c < 2; c++) {
        uint32_t Abase = smb + c * HSTAGE * 2;
        uint32_t Bbase = Abase + 128 * HPAD * 2;
        const __half* Ag = Ab + c * 64;
        const __half* Bg = Bb + c * 64;
#pragma unroll
        for (int i = 0; i < 4; i++) {
            int row = lrow + i * 32;
            uint32_t off = (uint32_t)(row * HPAD + lcg) * 2;
            cp_async16(Abase + off, Ag + (size_t)row * K + lcg);
            cp_async16(Bbase + off, Bg + (size_t)row * K + lcg);
        }
        asm volatile("cp.async.commit_group;\n");
    }

    int s = 0;  /* stage of chunk c */
    for (int c = 0; c < NC; c++) {
        asm volatile("cp.async.wait_group 1;\n");
        __syncthreads();

        // prefetch chunk c+2 into stage (s+2)%3 (holds chunk c-1, consumed)
        if (c + 2 < NC) {
            int sp = s + 2; if (sp >= HG_NSTAGE) sp -= HG_NSTAGE;
            uint32_t Abase = smb + sp * HSTAGE * 2;
            uint32_t Bbase = Abase + 128 * HPAD * 2;
            const __half* Ag = Ab + (c + 2) * 64;
            const __half* Bg = Bb + (c + 2) * 64;
#pragma unroll
            for (int i = 0; i < 4; i++) {
                int row = lrow + i * 32;
                uint32_t off = (uint32_t)(row * HPAD + lcg) * 2;
                cp_async16(Abase + off, Ag + (size_t)row * K + lcg);
                cp_async16(Bbase + off, Bg + (size_t)row * K + lcg);
            }
        }
        asm volatile("cp.async.commit_group;\n");

        uint32_t As_u = smb + s * HSTAGE * 2;
        uint32_t Bs_u = As_u + 128 * HPAD * 2;

#pragma unroll
        for (int ks = 0; ks < 4; ks++) {
            const int k = ks * 16;
            uint32_t a[2][4], b[8][2];
#pragma unroll
            for (int mt = 0; mt < 2; mt++) {
                uint32_t addr = As_u + (uint32_t)((wm + mt * 16 + a_row) * HPAD + k + a_col) * 2;
                ldsm_x4(a[mt][0], a[mt][1], a[mt][2], a[mt][3], addr);
            }
#pragma unroll
            for (int p = 0; p < 4; p++) {
                uint32_t addr = Bs_u + (uint32_t)((wn + p * 16 + b_row) * HPAD + k + b_col) * 2;
                ldsm_x4(b[2 * p][0], b[2 * p][1], b[2 * p + 1][0], b[2 * p + 1][1], addr);
            }
#pragma unroll
            for (int mt = 0; mt < 2; mt++)
#pragma unroll
                for (int nt = 0; nt < 8; nt++) {
                    asm volatile(
                        "mma.sync.aligned.m16n8k16.row.col.f32.f16.f16.f32 "
                        "{%0,%1,%2,%3}, {%4,%5,%6,%7}, {%8,%9}, {%0,%1,%2,%3};\n"
                        : "+f"(acc[mt][nt][0]), "+f"(acc[mt][nt][1]),
                          "+f"(acc[mt][nt][2]), "+f"(acc[mt][nt][3])
                        : "r"(a[mt][0]), "r"(a[mt][1]), "r"(a[mt][2]), "r"(a[mt][3]),
                          "r"(b[nt][0]), "r"(b[nt][1]));
                }
        }
        __syncthreads();
        if (++s == HG_NSTAGE) s = 0;
    }

    // epilogue: c0:(g,2t) c1:(g,2t+1) c2:(g+8,2t) c3:(g+8,2t+1)
#pragma unroll
    for (int mt = 0; mt < 2; mt++) {
        int r0 = bm * 128 + wm + mt * 16 + g;
#pragma unroll
        for (int nt = 0; nt < 8; nt++) {
            int c0 = bn * 128 + wn + nt * 8 + t * 2;
            *(float2*)(C + (size_t)r0 * N + c0)       = make_float2(acc[mt][nt][0], acc[mt][nt][1]);
            *(float2*)(C + (size_t)(r0 + 8) * N + c0) = make_float2(acc[mt][nt][2], acc[mt][nt][3]);
        }
    }
}

// fused Q/K/V projection: grid (18, 32). bn 0..15 -> Q tile; 16 -> K; 17 -> V
__global__ __launch_bounds__(256) void hgemm_qkv(const __half* __restrict__ A,
                                                 const __half* __restrict__ Bq,
                                                 const __half* __restrict__ Bk,
                                                 const __half* __restrict__ Bv,
                                                 float* __restrict__ Cq,
                                                 float* __restrict__ Ck,
                                                 float* __restrict__ Cv,
                                                 int K) {
    const int bn = blockIdx.x;
    if (bn < 16)      hgemm_body(A, Bq, Cq, HID, K, blockIdx.y, bn);
    else if (bn == 16) hgemm_body(A, Bk, Ck, HD, K, blockIdx.y, 0);
    else               hgemm_body(A, Bv, Cv, HD, K, blockIdx.y, 0);
}

__global__ __launch_bounds__(256) void hgemm(const __half* __restrict__ A,
                                             const __half* __restrict__ B,
                                             float* __restrict__ C,
                                             int N, int K) {
    hgemm_body(A, B, C, N, K, blockIdx.y, blockIdx.x);
}

// ---------------------------------------------------------------------------
// RoPE
// ---------------------------------------------------------------------------
__global__ void rope_q_kernel(float* __restrict__ q) {
    const int bs = blockIdx.x;
    const int h  = blockIdx.y;
    const int j  = threadIdx.x;
    const int s  = bs & (SEQ - 1);
    float inv = exp2f(-(float)j * LOG2_10000_DIV64);
    float sn, cs;
    sincosf((float)s * inv, &sn, &cs);
    float* row = q + ((size_t)bs * NH + h) * HD;
    float x1 = row[j], x2 = row[j + 64];
    row[j]      = x1 * cs - x2 * sn;
    row[j + 64] = x2 * cs + x1 * sn;
}

__global__ void rope_k_kernel(float* __restrict__ k) {
    const int bs = blockIdx.x;
    const int j  = threadIdx.x;
    const int s  = bs & (SEQ - 1);
    float inv = exp2f(-(float)j * LOG2_10000_DIV64);
    float sn, cs;
    sincosf((float)s * inv, &sn, &cs);
    float* row = k + (size_t)bs * HD;
    float x1 = row[j], x2 = row[j + 64];
    row[j]      = x1 * cs - x2 * sn;
    row[j + 64] = x2 * cs + x1 * sn;
}

// ===========================================================================
// fp16 tensor-core flash attention (validated R5/R6, unchanged)
// ===========================================================================
#define FTQ 64
#define FTK 32
#define NKT (SEQ / FTK)
#define KROW 68
#define VROW 20

__device__ __forceinline__ uint32_t pack_h2(float lo, float hi) {
    uint32_t r;
    asm("cvt.rn.f16x2.f32 %0, %1, %2;" : "=r"(r) : "f"(hi), "f"(lo));
    return r;
}

__global__ __launch_bounds__(128) void flash_fp16(const float* __restrict__ qb,
                                                  const float* __restrict__ kb,
                                                  const float* __restrict__ vb,
                                                  __half* __restrict__ ob) {
    __shared__ uint32_t Ks[FTK * KROW];
    __shared__ uint32_t Vs[HD * VROW];

    const int b = blockIdx.z, h = blockIdx.y, qt = blockIdx.x;
    const int tid = threadIdx.x, w = tid >> 5, lane = tid & 31;
    const int g = lane >> 2, t = lane & 3;

    uint32_t qf[8][4];
    {
        const float* Q0 = qb + ((size_t)(b * SEQ + qt * FTQ + w * 16 + g) * NH + h) * HD;
        const float* Q1 = Q0 + (size_t)8 * NH * HD;
#pragma unroll
        for (int ks = 0; ks < 8; ks++) {
            float2 x0 = *(const float2*)(Q0 + ks * 16 + 2 * t);
            float2 x1 = *(const float2*)(Q1 + ks * 16 + 2 * t);
            float2 x2 = *(const float2*)(Q0 + ks * 16 + 2 * t + 8);
            float2 x3 = *(const float2*)(Q1 + ks * 16 + 2 * t + 8);
            qf[ks][0] = pack_h2(x0.x, x0.y);
            qf[ks][1] = pack_h2(x1.x, x1.y);
            qf[ks][2] = pack_h2(x2.x, x2.y);
            qf[ks][3] = pack_h2(x3.x, x3.y);
        }
    }

    float acc[16][4];
#pragma unroll
    for (int nt = 0; nt < 16; nt++)
#pragma unroll
        for (int c = 0; c < 4; c++) acc[nt][c] = 0.f;
    float m0 = -1e30f, m1 = -1e30f, l0 = 0.f, l1 = 0.f;

    const int jrow = tid >> 2;
    const int qd   = (tid & 3) * 32;

    for (int it = 0; it < NKT; it++) {
        if (it) __syncthreads();
        {
            const float* Kg = kb + (size_t)(b * SEQ + it * FTK + jrow) * HD + qd;
            uint32_t* Kd = Ks + jrow * KROW + (qd >> 1);
#pragma unroll
            for (int i = 0; i < 8; i++) {
                float4 v = *(const float4*)(Kg + i * 4);
                Kd[i * 2 + 0] = pack_h2(v.x, v.y);
                Kd[i * 2 + 1] = pack_h2(v.z, v.w);
            }
            const float* Vg = vb + (size_t)(b * SEQ + it * FTK + jrow) * HD + qd;
            __half* Vh = (__half*)Vs;
#pragma unroll
            for (int i = 0; i < 8; i++) {
                float4 v = *(const float4*)(Vg + i * 4);
                Vh[(qd + i * 4 + 0) * (2 * VROW) + jrow] = __float2half(v.x);
                Vh[(qd + i * 4 + 1) * (2 * VROW) + jrow] = __float2half(v.y);
                Vh[(qd + i * 4 + 2) * (2 * VROW) + jrow] = __float2half(v.z);
                Vh[(qd + i * 4 + 3) * (2 * VROW) + jrow] = __float2half(v.w);
            }
        }
        __syncthreads();

        float sacc[4][4];
#pragma unroll
        for (int nt = 0; nt < 4; nt++)
#pragma unroll
            for (int c = 0; c < 4; c++) sacc[nt][c] = 0.f;

#pragma unroll
        for (int ks = 0; ks < 8; ks++) {
#pragma unroll
            for (int nt = 0; nt < 4; nt++) {
                uint32_t b0 = Ks[(nt * 8 + g) * KROW + ks * 8 + t];
                uint32_t b1 = Ks[(nt * 8 + g) * KROW + ks * 8 + t + 4];
                asm volatile(
                    "mma.sync.aligned.m16n8k16.row.col.f32.f16.f16.f32 "
                    "{%0,%1,%2,%3}, {%4,%5,%6,%7}, {%8,%9}, {%0,%1,%2,%3};\n"
                    : "+f"(sacc[nt][0]), "+f"(sacc[nt][1]),
                      "+f"(sacc[nt][2]), "+f"(sacc[nt][3])
                    : "r"(qf[ks][0]), "r"(qf[ks][1]), "r"(qf[ks][2]), "r"(qf[ks][3]),
                      "r"(b0), "r"(b1));
            }
        }

        float mx0 = sacc[0][0], mx1 = sacc[0][2];
#pragma unroll
        for (int nt = 0; nt < 4; nt++) {
            mx0 = fmaxf(mx0, fmaxf(sacc[nt][0], sacc[nt][1]));
            mx1 = fmaxf(mx1, fmaxf(sacc[nt][2], sacc[nt][3]));
        }
        mx0 = fmaxf(mx0, __shfl_xor_sync(0xffffffffu, mx0, 1));
        mx0 = fmaxf(mx0, __shfl_xor_sync(0xffffffffu, mx0, 2));
        mx1 = fmaxf(mx1, __shfl_xor_sync(0xffffffffu, mx1, 1));
        mx1 = fmaxf(mx1, __shfl_xor_sync(0xffffffffu, mx1, 2));

        float mn0 = fmaxf(m0, mx0), mn1 = fmaxf(m1, mx1);
        float sum0 = 0.f, sum1 = 0.f;
#pragma unroll
        for (int nt = 0; nt < 4; nt++) {
            sacc[nt][0] = __expf(sacc[nt][0] - mn0);
            sacc[nt][1] = __expf(sacc[nt][1] - mn0);
            sacc[nt][2] = __expf(sacc[nt][2] - mn1);
            sacc[nt][3] = __expf(sacc[nt][3] - mn1);
            sum0 += sacc[nt][0] + sacc[nt][1];
            sum1 += sacc[nt][2] + sacc[nt][3];
        }
        sum0 += __shfl_xor_sync(0xffffffffu, sum0, 1);
        sum0 += __shfl_xor_sync(0xffffffffu, sum0, 2);
        sum1 += __shfl_xor_sync(0xffffffffu, sum1, 1);
        sum1 += __shfl_xor_sync(0xffffffffu, sum1, 2);

        float c0 = __expf(m0 - mn0), c1 = __expf(m1 - mn1);
        l0 = l0 * c0 + sum0; l1 = l1 * c1 + sum1;
        m0 = mn0; m1 = mn1;
#pragma unroll
        for (int nt = 0; nt < 16; nt++) {
            acc[nt][0] *= c0; acc[nt][1] *= c0;
            acc[nt][2] *= c1; acc[nt][3] *= c1;
        }

        uint32_t pa[2][4];
#pragma unroll
        for (int k2 = 0; k2 < 2; k2++) {
            pa[k2][0] = pack_h2(sacc[2 * k2][0],     sacc[2 * k2][1]);
            pa[k2][1] = pack_h2(sacc[2 * k2][2],     sacc[2 * k2][3]);
            pa[k2][2] = pack_h2(sacc[2 * k2 + 1][0], sacc[2 * k2 + 1][1]);
            pa[k2][3] = pack_h2(sacc[2 * k2 + 1][2], sacc[2 * k2 + 1][3]);
        }

#pragma unroll
        for (int k2 = 0; k2 < 2; k2++) {
#pragma unroll
            for (int nt = 0; nt < 16; nt++) {
                uint32_t b0 = Vs[(nt * 8 + g) * VROW + k2 * 8 + t];
                uint32_t b1 = Vs[(nt * 8 + g) * VROW + k2 * 8 + t + 4];
                asm volatile(
                    "mma.sync.aligned.m16n8k16.row.col.f32.f16.f16.f32 "
                    "{%0,%1,%2,%3}, {%4,%5,%6,%7}, {%8,%9}, {%0,%1,%2,%3};\n"
                    : "+f"(acc[nt][0]), "+f"(acc[nt][1]),
                      "+f"(acc[nt][2]), "+f"(acc[nt][3])
                    : "r"(pa[k2][0]), "r"(pa[k2][1]), "r"(pa[k2][2]), "r"(pa[k2][3]),
                      "r"(b0), "r"(b1));
            }
        }
    }

    float il0 = 1.f / l0, il1 = 1.f / l1;
    __half* O0 = ob + ((size_t)(b * SEQ + qt * FTQ + w * 16 + g) * NH + h) * HD;
    __half* O1 = O0 + (size_t)8 * NH * HD;
#pragma unroll
    for (int nt = 0; nt < 16; nt++) {
        *(__half2*)(O0 + nt * 8 + 2 * t) = __floats2half2_rn(acc[nt][0] * il0, acc[nt][1] * il0);
        *(__half2*)(O1 + nt * 8 + 2 * t) = __floats2half2_rn(acc[nt][2] * il1, acc[nt][3] * il1);
    }
}

// ---------------------------------------------------------------------------
extern "C" void kernel_launch(void* const* d_in, const int* in_sizes, int n_in,
                              void* d_out, int out_size) {
    const float* x  = (const float*)d_in[0];
    const float* Wq = (const float*)d_in[1];
    const float* Wk = (const float*)d_in[2];
    const float* Wv = (const float*)d_in[3];
    const float* Wo = (const float*)d_in[4];
    float* out = (float*)d_out;

    float*  qbuf; cudaGetSymbolAddress((void**)&qbuf, g_qbuf);
    float*  kvfb; cudaGetSymbolAddress((void**)&kvfb, g_kvfb);
    __half* xh;   cudaGetSymbolAddress((void**)&xh,  g_xh);
    __half* wqh;  cudaGetSymbolAddress((void**)&wqh, g_wqh);
    __half* wkh;  cudaGetSymbolAddress((void**)&wkh, g_wkh);
    __half* wvh;  cudaGetSymbolAddress((void**)&wvh, g_wvh);
    __half* woh;  cudaGetSymbolAddress((void**)&woh, g_woh);
    __half* oh;   cudaGetSymbolAddress((void**)&oh,  g_oh);

    const size_t off_k = (size_t)MROWS * HID;
    const size_t off_v = off_k + (size_t)MROWS * HD;
    const size_t need  = off_v + (size_t)MROWS * HD;

    float* kout;
    float* vout;
    if ((size_t)out_size >= need) {
        kout = out + off_k;
        vout = out + off_v;
    } else {
        kout = kvfb;
        vout = kvfb + (size_t)MROWS * HD;
    }

    cudaFuncSetAttribute(hgemm_qkv, cudaFuncAttributeMaxDynamicSharedMemorySize, HG_SMEM);
    cudaFuncSetAttribute(hgemm,     cudaFuncAttributeMaxDynamicSharedMemorySize, HG_SMEM);

    f2h_kernel<<<(MROWS * HID / 4 + 255) / 256, 256>>>(x,  xh,  MROWS * HID / 4, 1.f);
    f2h_kernel<<<(HID * HID / 4 + 255) / 256, 256>>>(Wq, wqh, HID * HID / 4, QSCALE);
    f2h_kernel<<<(HD * HID / 4 + 255) / 256, 256>>>(Wk, wkh, HD * HID / 4, 1.f);
    f2h_kernel<<<(HD * HID / 4 + 255) / 256, 256>>>(Wv, wvh, HD * HID / 4, 1.f);
    f2h_kernel<<<(HID * HID / 4 + 255) / 256, 256>>>(Wo, woh, HID * HID / 4, 1.f);

    dim3 gqkv(18, MROWS / 128);             // (18, 32): 16 Q tiles + K + V
    dim3 gbig(HID / 128, MROWS / 128);      // (16, 32)

    hgemm_qkv<<<gqkv, 256, HG_SMEM>>>(xh, wqh, wkh, wvh, qbuf, kout, vout, HID);

    rope_q_kernel<<<dim3(MROWS, NH), 64>>>(qbuf);
    rope_k_kernel<<<MROWS, 64>>>(kout);

    flash_fp16<<<dim3(SEQ / FTQ, NH, NB), 128>>>(qbuf, kout, vout, oh);

    hgemm<<<gbig, 256, HG_SMEM>>>(oh, woh, out, HID, HID);
}

// round 12
// speedup vs baseline: 5.2258x; 1.3650x over previous
#include <cuda_runtime.h>
#include <cuda_fp16.h>
#include <math.h>
#include <stdint.h>

#define NB   2
#define SEQ  2048
#define HID  2048
#define NH   16
#define HD   128
#define MROWS (NB*SEQ)   /* 4096 */

// scratch (allocation-free: device globals)
__device__ float  g_kvfb[(size_t)2 * MROWS * HD];
__device__ __half g_xh [(size_t)MROWS * HID];
__device__ __half g_wqh[(size_t)HID * HID];      // Wq * QSCALE
__device__ __half g_wkh[(size_t)HD * HID];
__device__ __half g_wvh[(size_t)HD * HID];
__device__ __half g_woh[(size_t)HID * HID];
__device__ __half g_qh [(size_t)MROWS * HID];    // rope'd Q, fp16, [m, h*128+d]
__device__ __half g_kh [(size_t)MROWS * HD];     // rope'd K, fp16
__device__ __half g_vh [(size_t)MROWS * HD];     // V, fp16
__device__ __half g_oh [(size_t)MROWS * HID];    // attention out (fp16)
__device__ float2 g_ropetab[(size_t)SEQ * 64];   // (cos, sin) per (s, j)

#define QSCALE 0.08838834765f
#define LOG2_10000_DIV64 0.20762050593f

// ---------------------------------------------------------------------------
// One conversion kernel: x, 4 weights (fp32->fp16), rope table.
// grid (8192, 6), block 256.
// ---------------------------------------------------------------------------
__global__ void f2h_all(const float* __restrict__ x,  const float* __restrict__ Wq,
                        const float* __restrict__ Wk, const float* __restrict__ Wv,
                        const float* __restrict__ Wo) {
    const int i = blockIdx.x * 256 + threadIdx.x;
    const int seg = blockIdx.y;
    const float* in = nullptr; __half* outp = nullptr; int n4 = 0; float scale = 1.f;
    __half* xh;  __half* wqh; __half* wkh; __half* wvh; __half* woh;
    xh  = g_xh;  wqh = g_wqh; wkh = g_wkh; wvh = g_wvh; woh = g_woh;
    switch (seg) {
        case 0: in = x;  outp = xh;  n4 = MROWS * HID / 4; break;
        case 1: in = Wq; outp = wqh; n4 = HID * HID / 4; scale = QSCALE; break;
        case 2: in = Wk; outp = wkh; n4 = HD * HID / 4; break;
        case 3: in = Wv; outp = wvh; n4 = HD * HID / 4; break;
        case 4: in = Wo; outp = woh; n4 = HID * HID / 4; break;
        case 5: {
            if (i < SEQ * 64) {
                int s = i >> 6, j = i & 63;
                float inv = exp2f(-(float)j * LOG2_10000_DIV64);
                float sn, cs;
                sincosf((float)s * inv, &sn, &cs);
                g_ropetab[i] = make_float2(cs, sn);
            }
            return;
        }
    }
    if (i < n4) {
        float4 v = ((const float4*)in)[i];
        ((__half2*)outp)[2 * i + 0] = __floats2half2_rn(v.x * scale, v.y * scale);
        ((__half2*)outp)[2 * i + 1] = __floats2half2_rn(v.z * scale, v.w * scale);
    }
}

// ===========================================================================
// fp16 mma.sync GEMM NT, ldmatrix + 3-stage cp.async (mainloop as R10).
// Epilogue by MODE: 0 = fp32 C; 1 = rope -> fp16 Q; 2 = rope -> fp32+fp16 K;
// 3 = copy -> fp32+fp16 V.
// ===========================================================================
#define HPAD 72
#define HSTAGE (2 * 128 * HPAD)
#define HG_NSTAGE 3
#define HG_SMEM (HG_NSTAGE * HSTAGE * 2)   /* 110592 bytes */

__device__ __forceinline__ void cp_async16(uint32_t s, const void* g) {
    asm volatile("cp.async.cg.shared.global [%0], [%1], 16;\n" :: "r"(s), "l"(g));
}
__device__ __forceinline__ void ldsm_x4(uint32_t& r0, uint32_t& r1,
                                        uint32_t& r2, uint32_t& r3, uint32_t a) {
    asm volatile("ldmatrix.sync.aligned.m8n8.x4.shared.b16 {%0,%1,%2,%3}, [%4];"
                 : "=r"(r0), "=r"(r1), "=r"(r2), "=r"(r3) : "r"(a));
}

template<int MODE>
__device__ __forceinline__ void hgemm_body(const __half* __restrict__ A,
                                           const __half* __restrict__ Bw,
                                           float* __restrict__ Cf,
                                           __half* __restrict__ Ch,
                                           const float2* __restrict__ ropetab,
                                           int N, int K, int bm, int bn) {
    extern __shared__ __half hsm[];
    const int tid  = threadIdx.x;
    const int wid  = tid >> 5, lane = tid & 31;
    const int g    = lane >> 2, t = lane & 3;
    const int wm   = (wid & 3) * 32;
    const int wn   = (wid >> 2) * 64;

    const __half* Ab = A  + (size_t)bm * 128 * K;
    const __half* Bb = Bw + (size_t)bn * 128 * K;
    const int NC = K >> 6;

    float acc[2][8][4];
#pragma unroll
    for (int mt = 0; mt < 2; mt++)
#pragma unroll
        for (int nt = 0; nt < 8; nt++)
#pragma unroll
            for (int c = 0; c < 4; c++) acc[mt][nt][c] = 0.f;

    const uint32_t smb = (uint32_t)__cvta_generic_to_shared(hsm);
    const int lrow = tid >> 3, lcg = (tid & 7) * 8;

    const int a_row = (lane & 15), a_col = (lane >> 4) << 3;
    const int b_row = ((lane >> 4) << 3) + (lane & 7), b_col = ((lane >> 3) & 1) << 3;

#pragma unroll
    for (int c = 0; c < 2; c++) {
        uint32_t Abase = smb + c * HSTAGE * 2;
        uint32_t Bbase = Abase + 128 * HPAD * 2;
        const __half* Ag = Ab + c * 64;
        const __half* Bg = Bb + c * 64;
#pragma unroll
        for (int i = 0; i < 4; i++) {
            int row = lrow + i * 32;
            uint32_t off = (uint32_t)(row * HPAD + lcg) * 2;
            cp_async16(Abase + off, Ag + (size_t)row * K + lcg);
            cp_async16(Bbase + off, Bg + (size_t)row * K + lcg);
        }
        asm volatile("cp.async.commit_group;\n");
    }

    int s = 0;
    for (int c = 0; c < NC; c++) {
        asm volatile("cp.async.wait_group 1;\n");
        __syncthreads();

        if (c + 2 < NC) {
            int sp = s + 2; if (sp >= HG_NSTAGE) sp -= HG_NSTAGE;
            uint32_t Abase = smb + sp * HSTAGE * 2;
            uint32_t Bbase = Abase + 128 * HPAD * 2;
            const __half* Ag = Ab + (c + 2) * 64;
            const __half* Bg = Bb + (c + 2) * 64;
#pragma unroll
            for (int i = 0; i < 4; i++) {
                int row = lrow + i * 32;
                uint32_t off = (uint32_t)(row * HPAD + lcg) * 2;
                cp_async16(Abase + off, Ag + (size_t)row * K + lcg);
                cp_async16(Bbase + off, Bg + (size_t)row * K + lcg);
            }
        }
        asm volatile("cp.async.commit_group;\n");

        uint32_t As_u = smb + s * HSTAGE * 2;
        uint32_t Bs_u = As_u + 128 * HPAD * 2;

#pragma unroll
        for (int ks = 0; ks < 4; ks++) {
            const int k = ks * 16;
            uint32_t a[2][4], b[8][2];
#pragma unroll
            for (int mt = 0; mt < 2; mt++) {
                uint32_t addr = As_u + (uint32_t)((wm + mt * 16 + a_row) * HPAD + k + a_col) * 2;
                ldsm_x4(a[mt][0], a[mt][1], a[mt][2], a[mt][3], addr);
            }
#pragma unroll
            for (int p = 0; p < 4; p++) {
                uint32_t addr = Bs_u + (uint32_t)((wn + p * 16 + b_row) * HPAD + k + b_col) * 2;
                ldsm_x4(b[2 * p][0], b[2 * p][1], b[2 * p + 1][0], b[2 * p + 1][1], addr);
            }
#pragma unroll
            for (int mt = 0; mt < 2; mt++)
#pragma unroll
                for (int nt = 0; nt < 8; nt++) {
                    asm volatile(
                        "mma.sync.aligned.m16n8k16.row.col.f32.f16.f16.f32 "
                        "{%0,%1,%2,%3}, {%4,%5,%6,%7}, {%8,%9}, {%0,%1,%2,%3};\n"
                        : "+f"(acc[mt][nt][0]), "+f"(acc[mt][nt][1]),
                          "+f"(acc[mt][nt][2]), "+f"(acc[mt][nt][3])
                        : "r"(a[mt][0]), "r"(a[mt][1]), "r"(a[mt][2]), "r"(a[mt][3]),
                          "r"(b[nt][0]), "r"(b[nt][1]));
                }
        }
        __syncthreads();
        if (++s == HG_NSTAGE) s = 0;
    }

    if (MODE == 0) {
#pragma unroll
        for (int mt = 0; mt < 2; mt++) {
            int r0 = bm * 128 + wm + mt * 16 + g;
#pragma unroll
            for (int nt = 0; nt < 8; nt++) {
                int c0 = bn * 128 + wn + nt * 8 + t * 2;
                *(float2*)(Cf + (size_t)r0 * N + c0)       = make_float2(acc[mt][nt][0], acc[mt][nt][1]);
                *(float2*)(Cf + (size_t)(r0 + 8) * N + c0) = make_float2(acc[mt][nt][2], acc[mt][nt][3]);
            }
        }
        return;
    }

    // staged epilogue with rope / fp16 conversion
    float* sst = (float*)hsm;           /* 128 x 132 fp32 = 67.6KB (pipeline done) */
#pragma unroll
    for (int mt = 0; mt < 2; mt++) {
        int r0 = wm + mt * 16 + g;
#pragma unroll
        for (int nt = 0; nt < 8; nt++) {
            int c0 = wn + nt * 8 + t * 2;
            *(float2*)(sst + r0 * 132 + c0)       = make_float2(acc[mt][nt][0], acc[mt][nt][1]);
            *(float2*)(sst + (r0 + 8) * 132 + c0) = make_float2(acc[mt][nt][2], acc[mt][nt][3]);
        }
    }
    __syncthreads();

#pragma unroll 4
    for (int p = 0; p < 32; p++) {
        int idx = tid + p * 256;             /* 0..8191 */
        int row = idx >> 6, d = idx & 63;
        int m = bm * 128 + row;
        float x1 = sst[row * 132 + d], x2 = sst[row * 132 + d + 64];
        float y1, y2;
        if (MODE == 3) { y1 = x1; y2 = x2; }
        else {
            float2 cssn = ropetab[(m & (SEQ - 1)) * 64 + d];
            y1 = x1 * cssn.x - x2 * cssn.y;
            y2 = x2 * cssn.x + x1 * cssn.y;
        }
        if (MODE >= 2) {
            Cf[(size_t)m * HD + d]      = y1;
            Cf[(size_t)m * HD + d + 64] = y2;
            Ch[(size_t)m * HD + d]      = __float2half(y1);
            Ch[(size_t)m * HD + d + 64] = __float2half(y2);
        } else {
            __half* base = Ch + (size_t)m * HID + bn * 128;
            base[d]      = __float2half(y1);
            base[d + 64] = __float2half(y2);
        }
    }
}

// fused Q/K/V projection: grid (18, 32). bn 0..15 -> Q; 16 -> K; 17 -> V
__global__ __launch_bounds__(256) void hgemm_qkv(const __half* __restrict__ A,
                                                 const __half* __restrict__ Bq,
                                                 const __half* __restrict__ Bk,
                                                 const __half* __restrict__ Bv,
                                                 __half* __restrict__ qh,
                                                 float* __restrict__ kout,
                                                 __half* __restrict__ kh,
                                                 float* __restrict__ vout,
                                                 __half* __restrict__ vh,
                                                 const float2* __restrict__ ropetab,
                                                 int K) {
    const int bn = blockIdx.x;
    if (bn < 16)
        hgemm_body<1>(A, Bq, nullptr, qh, ropetab, HID, K, blockIdx.y, bn);
    else if (bn == 16)
        hgemm_body<2>(A, Bk, kout, kh, ropetab, HD, K, blockIdx.y, 0);
    else
        hgemm_body<3>(A, Bv, vout, vh, ropetab, HD, K, blockIdx.y, 0);
}

__global__ __launch_bounds__(256) void hgemm_plain(const __half* __restrict__ A,
                                                   const __half* __restrict__ B,
                                                   float* __restrict__ C,
                                                   int N, int K) {
    hgemm_body<0>(A, B, C, nullptr, nullptr, N, K, blockIdx.y, blockIdx.x);
}

// ===========================================================================
// fp16 flash attention — all-fp16 inputs now (qh/kh/vh)
// ===========================================================================
#define FTQ 64
#define FTK 32
#define NKT (SEQ / FTK)
#define KROW 68
#define VROW 20

__device__ __forceinline__ uint32_t pack_h2(float lo, float hi) {
    uint32_t r;
    asm("cvt.rn.f16x2.f32 %0, %1, %2;" : "=r"(r) : "f"(hi), "f"(lo));
    return r;
}

__global__ __launch_bounds__(128) void flash_fp16(const __half* __restrict__ qh,
                                                  const __half* __restrict__ kh,
                                                  const __half* __restrict__ vh,
                                                  __half* __restrict__ ob) {
    __shared__ uint32_t Ks[FTK * KROW];
    __shared__ uint32_t Vs[HD * VROW];

    const int b = blockIdx.z, h = blockIdx.y, qt = blockIdx.x;
    const int tid = threadIdx.x, w = tid >> 5, lane = tid & 31;
    const int g = lane >> 2, t = lane & 3;

    uint32_t qf[8][4];
    {
        const __half* Q0 = qh + (size_t)(b * SEQ + qt * FTQ + w * 16 + g) * HID + h * HD;
        const __half* Q1 = Q0 + (size_t)8 * HID;
#pragma unroll
        for (int ks = 0; ks < 8; ks++) {
            qf[ks][0] = *(const uint32_t*)(Q0 + ks * 16 + 2 * t);
            qf[ks][1] = *(const uint32_t*)(Q1 + ks * 16 + 2 * t);
            qf[ks][2] = *(const uint32_t*)(Q0 + ks * 16 + 2 * t + 8);
            qf[ks][3] = *(const uint32_t*)(Q1 + ks * 16 + 2 * t + 8);
        }
    }

    float acc[16][4];
#pragma unroll
    for (int nt = 0; nt < 16; nt++)
#pragma unroll
        for (int c = 0; c < 4; c++) acc[nt][c] = 0.f;
    float m0 = -1e30f, m1 = -1e30f, l0 = 0.f, l1 = 0.f;

    const int jrow = tid >> 2;           /* 0..31 */
    const int qd   = (tid & 3) * 32;     /* 0,32,64,96 */

    for (int it = 0; it < NKT; it++) {
        if (it) __syncthreads();
        {
            const uint4* Kg = (const uint4*)(kh + (size_t)(b * SEQ + it * FTK + jrow) * HD + qd);
            uint32_t* Kd = Ks + jrow * KROW + (qd >> 1);
#pragma unroll
            for (int i = 0; i < 4; i++) {
                uint4 v = Kg[i];
                Kd[i * 4 + 0] = v.x; Kd[i * 4 + 1] = v.y;
                Kd[i * 4 + 2] = v.z; Kd[i * 4 + 3] = v.w;
            }
            const uint4* Vg = (const uint4*)(vh + (size_t)(b * SEQ + it * FTK + jrow) * HD + qd);
            __half* Vh = (__half*)Vs;
#pragma unroll
            for (int i = 0; i < 4; i++) {
                uint4 v = Vg[i];
                const __half* hv = (const __half*)&v;
#pragma unroll
                for (int k = 0; k < 8; k++)
                    Vh[(qd + i * 8 + k) * (2 * VROW) + jrow] = hv[k];
            }
        }
        __syncthreads();

        float sacc[4][4];
#pragma unroll
        for (int nt = 0; nt < 4; nt++)
#pragma unroll
            for (int c = 0; c < 4; c++) sacc[nt][c] = 0.f;

#pragma unroll
        for (int ks = 0; ks < 8; ks++) {
#pragma unroll
            for (int nt = 0; nt < 4; nt++) {
                uint32_t b0 = Ks[(nt * 8 + g) * KROW + ks * 8 + t];
                uint32_t b1 = Ks[(nt * 8 + g) * KROW + ks * 8 + t + 4];
                asm volatile(
                    "mma.sync.aligned.m16n8k16.row.col.f32.f16.f16.f32 "
                    "{%0,%1,%2,%3}, {%4,%5,%6,%7}, {%8,%9}, {%0,%1,%2,%3};\n"
                    : "+f"(sacc[nt][0]), "+f"(sacc[nt][1]),
                      "+f"(sacc[nt][2]), "+f"(sacc[nt][3])
                    : "r"(qf[ks][0]), "r"(qf[ks][1]), "r"(qf[ks][2]), "r"(qf[ks][3]),
                      "r"(b0), "r"(b1));
            }
        }

        float mx0 = sacc[0][0], mx1 = sacc[0][2];
#pragma unroll
        for (int nt = 0; nt < 4; nt++) {
            mx0 = fmaxf(mx0, fmaxf(sacc[nt][0], sacc[nt][1]));
            mx1 = fmaxf(mx1, fmaxf(sacc[nt][2], sacc[nt][3]));
        }
        mx0 = fmaxf(mx0, __shfl_xor_sync(0xffffffffu, mx0, 1));
        mx0 = fmaxf(mx0, __shfl_xor_sync(0xffffffffu, mx0, 2));
        mx1 = fmaxf(mx1, __shfl_xor_sync(0xffffffffu, mx1, 1));
        mx1 = fmaxf(mx1, __shfl_xor_sync(0xffffffffu, mx1, 2));

        float mn0 = fmaxf(m0, mx0), mn1 = fmaxf(m1, mx1);
        float sum0 = 0.f, sum1 = 0.f;
#pragma unroll
        for (int nt = 0; nt < 4; nt++) {
            sacc[nt][0] = __expf(sacc[nt][0] - mn0);
            sacc[nt][1] = __expf(sacc[nt][1] - mn0);
            sacc[nt][2] = __expf(sacc[nt][2] - mn1);
            sacc[nt][3] = __expf(sacc[nt][3] - mn1);
            sum0 += sacc[nt][0] + sacc[nt][1];
            sum1 += sacc[nt][2] + sacc[nt][3];
        }
        sum0 += __shfl_xor_sync(0xffffffffu, sum0, 1);
        sum0 += __shfl_xor_sync(0xffffffffu, sum0, 2);
        sum1 += __shfl_xor_sync(0xffffffffu, sum1, 1);
        sum1 += __shfl_xor_sync(0xffffffffu, sum1, 2);

        float c0 = __expf(m0 - mn0), c1 = __expf(m1 - mn1);
        l0 = l0 * c0 + sum0; l1 = l1 * c1 + sum1;
        m0 = mn0; m1 = mn1;
#pragma unroll
        for (int nt = 0; nt < 16; nt++) {
            acc[nt][0] *= c0; acc[nt][1] *= c0;
            acc[nt][2] *= c1; acc[nt][3] *= c1;
        }

        uint32_t pa[2][4];
#pragma unroll
        for (int k2 = 0; k2 < 2; k2++) {
            pa[k2][0] = pack_h2(sacc[2 * k2][0],     sacc[2 * k2][1]);
            pa[k2][1] = pack_h2(sacc[2 * k2][2],     sacc[2 * k2][3]);
            pa[k2][2] = pack_h2(sacc[2 * k2 + 1][0], sacc[2 * k2 + 1][1]);
            pa[k2][3] = pack_h2(sacc[2 * k2 + 1][2], sacc[2 * k2 + 1][3]);
        }

#pragma unroll
        for (int k2 = 0; k2 < 2; k2++) {
#pragma unroll
            for (int nt = 0; nt < 16; nt++) {
                uint32_t b0 = Vs[(nt * 8 + g) * VROW + k2 * 8 + t];
                uint32_t b1 = Vs[(nt * 8 + g) * VROW + k2 * 8 + t + 4];
                asm volatile(
                    "mma.sync.aligned.m16n8k16.row.col.f32.f16.f16.f32 "
                    "{%0,%1,%2,%3}, {%4,%5,%6,%7}, {%8,%9}, {%0,%1,%2,%3};\n"
                    : "+f"(acc[nt][0]), "+f"(acc[nt][1]),
                      "+f"(acc[nt][2]), "+f"(acc[nt][3])
                    : "r"(pa[k2][0]), "r"(pa[k2][1]), "r"(pa[k2][2]), "r"(pa[k2][3]),
                      "r"(b0), "r"(b1));
            }
        }
    }

    float il0 = 1.f / l0, il1 = 1.f / l1;
    __half* O0 = ob + (size_t)(b * SEQ + qt * FTQ + w * 16 + g) * HID + h * HD;
    __half* O1 = O0 + (size_t)8 * HID;
#pragma unroll
    for (int nt = 0; nt < 16; nt++) {
        *(__half2*)(O0 + nt * 8 + 2 * t) = __floats2half2_rn(acc[nt][0] * il0, acc[nt][1] * il0);
        *(__half2*)(O1 + nt * 8 + 2 * t) = __floats2half2_rn(acc[nt][2] * il1, acc[nt][3] * il1);
    }
}

// ---------------------------------------------------------------------------
extern "C" void kernel_launch(void* const* d_in, const int* in_sizes, int n_in,
                              void* d_out, int out_size) {
    const float* x  = (const float*)d_in[0];
    const float* Wq = (const float*)d_in[1];
    const float* Wk = (const float*)d_in[2];
    const float* Wv = (const float*)d_in[3];
    const float* Wo = (const float*)d_in[4];
    float* out = (float*)d_out;

    float*  kvfb; cudaGetSymbolAddress((void**)&kvfb, g_kvfb);
    __half* xh;   cudaGetSymbolAddress((void**)&xh,  g_xh);
    __half* wqh;  cudaGetSymbolAddress((void**)&wqh, g_wqh);
    __half* wkh;  cudaGetSymbolAddress((void**)&wkh, g_wkh);
    __half* wvh;  cudaGetSymbolAddress((void**)&wvh, g_wvh);
    __half* woh;  cudaGetSymbolAddress((void**)&woh, g_woh);
    __half* qh;   cudaGetSymbolAddress((void**)&qh,  g_qh);
    __half* kh;   cudaGetSymbolAddress((void**)&kh,  g_kh);
    __half* vh;   cudaGetSymbolAddress((void**)&vh,  g_vh);
    __half* oh;   cudaGetSymbolAddress((void**)&oh,  g_oh);
    float2* rtab; cudaGetSymbolAddress((void**)&rtab, g_ropetab);

    const size_t off_k = (size_t)MROWS * HID;
    const size_t off_v = off_k + (size_t)MROWS * HD;
    const size_t need  = off_v + (size_t)MROWS * HD;

    float* kout;
    float* vout;
    if ((size_t)out_size >= need) {
        kout = out + off_k;
        vout = out + off_v;
    } else {
        kout = kvfb;
        vout = kvfb + (size_t)MROWS * HD;
    }

    cudaFuncSetAttribute(hgemm_qkv,   cudaFuncAttributeMaxDynamicSharedMemorySize, HG_SMEM);
    cudaFuncSetAttribute(hgemm_plain, cudaFuncAttributeMaxDynamicSharedMemorySize, HG_SMEM);

    // (0) conversions + rope table
    f2h_all<<<dim3(8192, 6), 256>>>(x, Wq, Wk, Wv, Wo);

    // (1) fused QKV projection + rope + fp16 outputs
    hgemm_qkv<<<dim3(18, MROWS / 128), 256, HG_SMEM>>>(
        xh, wqh, wkh, wvh, qh, kout, kh, vout, vh, rtab, HID);

    // (2) flash attention (all-fp16 inputs)
    flash_fp16<<<dim3(SEQ / FTQ, NH, NB), 128>>>(qh, kh, vh, oh);

    // (3) O projection — launch index 3: profiled by ncu next round
    hgemm_plain<<<dim3(HID / 128, MROWS / 128), 256, HG_SMEM>>>(oh, woh, out, HID, HID);
}

// round 17
// speedup vs baseline: 7.4717x; 1.4298x over previous
#include <cuda_runtime.h>
#include <cuda_fp16.h>
#include <math.h>
#include <stdint.h>

#define NB   2
#define SEQ  2048
#define HID  2048
#define NH   16
#define HD   128
#define MROWS (NB*SEQ)   /* 4096 */

// scratch (allocation-free: device globals)
__device__ float  g_kvfb[(size_t)2 * MROWS * HD];
__device__ __half g_xh [(size_t)MROWS * HID];
__device__ __half g_wqh[(size_t)HID * HID];      // Wq * QSCALE
__device__ __half g_wkh[(size_t)HD * HID];
__device__ __half g_wvh[(size_t)HD * HID];
__device__ __half g_woh[(size_t)HID * HID];
__device__ __half g_qh [(size_t)MROWS * HID];    // rope'd Q, fp16, [m, h*128+d]
__device__ __half g_kh [(size_t)MROWS * HD];     // rope'd K, fp16
__device__ __half g_vh [(size_t)MROWS * HD];     // V, fp16
__device__ __half g_oh [(size_t)MROWS * HID];    // attention out (fp16)
__device__ float2 g_ropetab[(size_t)SEQ * 64];   // (cos, sin) per (s, j)

#define QSCALE 0.08838834765f
#define LOG2_10000_DIV64 0.20762050593f

// ---------------------------------------------------------------------------
// One conversion kernel: x, 4 weights (fp32->fp16), rope table.
// ---------------------------------------------------------------------------
__global__ void f2h_all(const float* __restrict__ x,  const float* __restrict__ Wq,
                        const float* __restrict__ Wk, const float* __restrict__ Wv,
                        const float* __restrict__ Wo) {
    const int i = blockIdx.x * 256 + threadIdx.x;
    const int seg = blockIdx.y;
    const float* in = nullptr; __half* outp = nullptr; int n4 = 0; float scale = 1.f;
    switch (seg) {
        case 0: in = x;  outp = g_xh;  n4 = MROWS * HID / 4; break;
        case 1: in = Wq; outp = g_wqh; n4 = HID * HID / 4; scale = QSCALE; break;
        case 2: in = Wk; outp = g_wkh; n4 = HD * HID / 4; break;
        case 3: in = Wv; outp = g_wvh; n4 = HD * HID / 4; break;
        case 4: in = Wo; outp = g_woh; n4 = HID * HID / 4; break;
        case 5: {
            if (i < SEQ * 64) {
                int s = i >> 6, j = i & 63;
                float inv = exp2f(-(float)j * LOG2_10000_DIV64);
                float sn, cs;
                sincosf((float)s * inv, &sn, &cs);
                g_ropetab[i] = make_float2(cs, sn);
            }
            return;
        }
    }
    if (i < n4) {
        float4 v = ((const float4*)in)[i];
        ((__half2*)outp)[2 * i + 0] = __floats2half2_rn(v.x * scale, v.y * scale);
        ((__half2*)outp)[2 * i + 1] = __floats2half2_rn(v.z * scale, v.w * scale);
    }
}

// ===========================================================================
// fp16 mma.sync GEMM NT, ldmatrix + 3-stage cp.async.
// __launch_bounds__(256,2): cap regs at 128 so 2 CTAs/SM co-reside.
// ===========================================================================
#define HPAD 72
#define HSTAGE (2 * 128 * HPAD)
#define HG_NSTAGE 3
#define HG_SMEM (HG_NSTAGE * HSTAGE * 2)   /* 110592 bytes */

__device__ __forceinline__ void cp_async16(uint32_t s, const void* g) {
    asm volatile("cp.async.cg.shared.global [%0], [%1], 16;\n" :: "r"(s), "l"(g));
}
__device__ __forceinline__ void ldsm_x4(uint32_t& r0, uint32_t& r1,
                                        uint32_t& r2, uint32_t& r3, uint32_t a) {
    asm volatile("ldmatrix.sync.aligned.m8n8.x4.shared.b16 {%0,%1,%2,%3}, [%4];"
                 : "=r"(r0), "=r"(r1), "=r"(r2), "=r"(r3) : "r"(a));
}
__device__ __forceinline__ void ldsm_x4_t(uint32_t& r0, uint32_t& r1,
                                          uint32_t& r2, uint32_t& r3, uint32_t a) {
    asm volatile("ldmatrix.sync.aligned.m8n8.x4.trans.shared.b16 {%0,%1,%2,%3}, [%4];"
                 : "=r"(r0), "=r"(r1), "=r"(r2), "=r"(r3) : "r"(a));
}

template<int MODE>
__device__ __forceinline__ void hgemm_body(const __half* __restrict__ A,
                                           const __half* __restrict__ Bw,
                                           float* __restrict__ Cf,
                                           __half* __restrict__ Ch,
                                           const float2* __restrict__ ropetab,
                                           int N, int K, int bm, int bn) {
    extern __shared__ __half hsm[];
    const int tid  = threadIdx.x;
    const int wid  = tid >> 5, lane = tid & 31;
    const int g    = lane >> 2, t = lane & 3;
    const int wm   = (wid & 3) * 32;
    const int wn   = (wid >> 2) * 64;

    const __half* Ab = A  + (size_t)bm * 128 * K;
    const __half* Bb = Bw + (size_t)bn * 128 * K;
    const int NC = K >> 6;

    float acc[2][8][4];
#pragma unroll
    for (int mt = 0; mt < 2; mt++)
#pragma unroll
        for (int nt = 0; nt < 8; nt++)
#pragma unroll
            for (int c = 0; c < 4; c++) acc[mt][nt][c] = 0.f;

    const uint32_t smb = (uint32_t)__cvta_generic_to_shared(hsm);
    const int lrow = tid >> 3, lcg = (tid & 7) * 8;

    const int a_row = (lane & 15), a_col = (lane >> 4) << 3;
    const int b_row = ((lane >> 4) << 3) + (lane & 7), b_col = ((lane >> 3) & 1) << 3;

#pragma unroll
    for (int c = 0; c < 2; c++) {
        uint32_t Abase = smb + c * HSTAGE * 2;
        uint32_t Bbase = Abase + 128 * HPAD * 2;
        const __half* Ag = Ab + c * 64;
        const __half* Bg = Bb + c * 64;
#pragma unroll
        for (int i = 0; i < 4; i++) {
            int row = lrow + i * 32;
            uint32_t off = (uint32_t)(row * HPAD + lcg) * 2;
            cp_async16(Abase + off, Ag + (size_t)row * K + lcg);
            cp_async16(Bbase + off, Bg + (size_t)row * K + lcg);
        }
        asm volatile("cp.async.commit_group;\n");
    }

    int s = 0;
    for (int c = 0; c < NC; c++) {
        asm volatile("cp.async.wait_group 1;\n");
        __syncthreads();

        if (c + 2 < NC) {
            int sp = s + 2; if (sp >= HG_NSTAGE) sp -= HG_NSTAGE;
            uint32_t Abase = smb + sp * HSTAGE * 2;
            uint32_t Bbase = Abase + 128 * HPAD * 2;
            const __half* Ag = Ab + (c + 2) * 64;
            const __half* Bg = Bb + (c + 2) * 64;
#pragma unroll
            for (int i = 0; i < 4; i++) {
                int row = lrow + i * 32;
                uint32_t off = (uint32_t)(row * HPAD + lcg) * 2;
                cp_async16(Abase + off, Ag + (size_t)row * K + lcg);
                cp_async16(Bbase + off, Bg + (size_t)row * K + lcg);
            }
        }
        asm volatile("cp.async.commit_group;\n");

        uint32_t As_u = smb + s * HSTAGE * 2;
        uint32_t Bs_u = As_u + 128 * HPAD * 2;

#pragma unroll
        for (int ks = 0; ks < 4; ks++) {
            const int k = ks * 16;
            uint32_t a[2][4], b[8][2];
#pragma unroll
            for (int mt = 0; mt < 2; mt++) {
                uint32_t addr = As_u + (uint32_t)((wm + mt * 16 + a_row) * HPAD + k + a_col) * 2;
                ldsm_x4(a[mt][0], a[mt][1], a[mt][2], a[mt][3], addr);
            }
#pragma unroll
            for (int p = 0; p < 4; p++) {
                uint32_t addr = Bs_u + (uint32_t)((wn + p * 16 + b_row) * HPAD + k + b_col) * 2;
                ldsm_x4(b[2 * p][0], b[2 * p][1], b[2 * p + 1][0], b[2 * p + 1][1], addr);
            }
#pragma unroll
            for (int mt = 0; mt < 2; mt++)
#pragma unroll
                for (int nt = 0; nt < 8; nt++) {
                    asm volatile(
                        "mma.sync.aligned.m16n8k16.row.col.f32.f16.f16.f32 "
                        "{%0,%1,%2,%3}, {%4,%5,%6,%7}, {%8,%9}, {%0,%1,%2,%3};\n"
                        : "+f"(acc[mt][nt][0]), "+f"(acc[mt][nt][1]),
                          "+f"(acc[mt][nt][2]), "+f"(acc[mt][nt][3])
                        : "r"(a[mt][0]), "r"(a[mt][1]), "r"(a[mt][2]), "r"(a[mt][3]),
                          "r"(b[nt][0]), "r"(b[nt][1]));
                }
        }
        __syncthreads();
        if (++s == HG_NSTAGE) s = 0;
    }

    if (MODE == 0) {
#pragma unroll
        for (int mt = 0; mt < 2; mt++) {
            int r0 = bm * 128 + wm + mt * 16 + g;
#pragma unroll
            for (int nt = 0; nt < 8; nt++) {
                int c0 = bn * 128 + wn + nt * 8 + t * 2;
                *(float2*)(Cf + (size_t)r0 * N + c0)       = make_float2(acc[mt][nt][0], acc[mt][nt][1]);
                *(float2*)(Cf + (size_t)(r0 + 8) * N + c0) = make_float2(acc[mt][nt][2], acc[mt][nt][3]);
            }
        }
        return;
    }

    float* sst = (float*)hsm;
#pragma unroll
    for (int mt = 0; mt < 2; mt++) {
        int r0 = wm + mt * 16 + g;
#pragma unroll
        for (int nt = 0; nt < 8; nt++) {
            int c0 = wn + nt * 8 + t * 2;
            *(float2*)(sst + r0 * 132 + c0)       = make_float2(acc[mt][nt][0], acc[mt][nt][1]);
            *(float2*)(sst + (r0 + 8) * 132 + c0) = make_float2(acc[mt][nt][2], acc[mt][nt][3]);
        }
    }
    __syncthreads();

#pragma unroll 4
    for (int p = 0; p < 32; p++) {
        int idx = tid + p * 256;
        int row = idx >> 6, d = idx & 63;
        int m = bm * 128 + row;
        float x1 = sst[row * 132 + d], x2 = sst[row * 132 + d + 64];
        float y1, y2;
        if (MODE == 3) { y1 = x1; y2 = x2; }
        else {
            float2 cssn = ropetab[(m & (SEQ - 1)) * 64 + d];
            y1 = x1 * cssn.x - x2 * cssn.y;
            y2 = x2 * cssn.x + x1 * cssn.y;
        }
        if (MODE >= 2) {
            Cf[(size_t)m * HD + d]      = y1;
            Cf[(size_t)m * HD + d + 64] = y2;
            Ch[(size_t)m * HD + d]      = __float2half(y1);
            Ch[(size_t)m * HD + d + 64] = __float2half(y2);
        } else {
            __half* base = Ch + (size_t)m * HID + bn * 128;
            base[d]      = __float2half(y1);
            base[d + 64] = __float2half(y2);
        }
    }
}

__global__ __launch_bounds__(256, 2) void hgemm_qkv(const __half* __restrict__ A,
                                                 const __half* __restrict__ Bq,
                                                 const __half* __restrict__ Bk,
                                                 const __half* __restrict__ Bv,
                                                 __half* __restrict__ qh,
                                                 float* __restrict__ kout,
                                                 __half* __restrict__ kh,
                                                 float* __restrict__ vout,
                                                 __half* __restrict__ vh,
                                                 const float2* __restrict__ ropetab,
                                                 int K) {
    const int bn = blockIdx.x;
    if (bn < 16)
        hgemm_body<1>(A, Bq, nullptr, qh, ropetab, HID, K, blockIdx.y, bn);
    else if (bn == 16)
        hgemm_body<2>(A, Bk, kout, kh, ropetab, HD, K, blockIdx.y, 0);
    else
        hgemm_body<3>(A, Bv, vout, vh, ropetab, HD, K, blockIdx.y, 0);
}

__global__ __launch_bounds__(256, 2) void hgemm_plain(const __half* __restrict__ A,
                                                   const __half* __restrict__ B,
                                                   float* __restrict__ C,
                                                   int N, int K) {
    hgemm_body<0>(A, B, C, nullptr, nullptr, N, K, blockIdx.y, blockIdx.x);
}

// ===========================================================================
// fp16 flash attention — warp = head. CTA: 8 heads x 16 q-rows; K/V smem
// shared across heads. V untransposed; AV B-fragments via ldmatrix.x4.trans.
// ===========================================================================
#define FTK 32
#define NKT (SEQ / FTK)
#define KROWU 68                 /* uint32 stride per key row (128+8 halves) */

__device__ __forceinline__ uint32_t pack_h2(float lo, float hi) {
    uint32_t r;
    asm("cvt.rn.f16x2.f32 %0, %1, %2;" : "=r"(r) : "f"(hi), "f"(lo));
    return r;
}

__global__ __launch_bounds__(256) void flash_fp16(const __half* __restrict__ qh,
                                                  const __half* __restrict__ kh,
                                                  const __half* __restrict__ vh,
                                                  __half* __restrict__ ob) {
    __shared__ uint32_t Ks[FTK * KROWU];
    __shared__ uint32_t Vs[FTK * KROWU];

    const int b = blockIdx.z, qt = blockIdx.x;
    const int tid = threadIdx.x, w = tid >> 5, lane = tid & 31;
    const int g = lane >> 2, t = lane & 3;
    const int h = blockIdx.y * 8 + w;

    // Q fragments for this warp's head: rows qt*16 + g and +8
    uint32_t qf[8][4];
    {
        const __half* Q0 = qh + (size_t)(b * SEQ + qt * 16 + g) * HID + h * HD;
        const __half* Q1 = Q0 + (size_t)8 * HID;
#pragma unroll
        for (int ks = 0; ks < 8; ks++) {
            qf[ks][0] = *(const uint32_t*)(Q0 + ks * 16 + 2 * t);
            qf[ks][1] = *(const uint32_t*)(Q1 + ks * 16 + 2 * t);
            qf[ks][2] = *(const uint32_t*)(Q0 + ks * 16 + 2 * t + 8);
            qf[ks][3] = *(const uint32_t*)(Q1 + ks * 16 + 2 * t + 8);
        }
    }

    float acc[16][4];
#pragma unroll
    for (int nt = 0; nt < 16; nt++)
#pragma unroll
        for (int c = 0; c < 4; c++) acc[nt][c] = 0.f;
    float m0 = -1e30f, m1 = -1e30f, l0 = 0.f, l1 = 0.f;

    // loaders: 256 threads, each (key-row, 16-half column segment)
    const int jrow = tid >> 3;             /* 0..31 */
    const int c16  = (tid & 7) * 16;       /* 0,16,...,112 halves */
    const uint32_t vsb = (uint32_t)__cvta_generic_to_shared(Vs);

    for (int it = 0; it < NKT; it++) {
        if (it) __syncthreads();
        {
            const uint4* Kg = (const uint4*)(kh + (size_t)(b * SEQ + it * FTK + jrow) * HD + c16);
            uint4 k0 = Kg[0], k1 = Kg[1];
            const uint4* Vg = (const uint4*)(vh + (size_t)(b * SEQ + it * FTK + jrow) * HD + c16);
            uint4 v0 = Vg[0], v1 = Vg[1];
            uint32_t* Kd = Ks + jrow * KROWU + (c16 >> 1);
            Kd[0] = k0.x; Kd[1] = k0.y; Kd[2] = k0.z; Kd[3] = k0.w;
            Kd[4] = k1.x; Kd[5] = k1.y; Kd[6] = k1.z; Kd[7] = k1.w;
            uint32_t* Vd = Vs + jrow * KROWU + (c16 >> 1);
            Vd[0] = v0.x; Vd[1] = v0.y; Vd[2] = v0.z; Vd[3] = v0.w;
            Vd[4] = v1.x; Vd[5] = v1.y; Vd[6] = v1.z; Vd[7] = v1.w;
        }
        __syncthreads();

        // ---- S = Q K^T (m16 x n32, 8 k16 steps)
        float sacc[4][4];
#pragma unroll
        for (int nt = 0; nt < 4; nt++)
#pragma unroll
            for (int c = 0; c < 4; c++) sacc[nt][c] = 0.f;

#pragma unroll
        for (int ks = 0; ks < 8; ks++) {
#pragma unroll
            for (int nt = 0; nt < 4; nt++) {
                uint32_t b0 = Ks[(nt * 8 + g) * KROWU + ks * 8 + t];
                uint32_t b1 = Ks[(nt * 8 + g) * KROWU + ks * 8 + t + 4];
                asm volatile(
                    "mma.sync.aligned.m16n8k16.row.col.f32.f16.f16.f32 "
                    "{%0,%1,%2,%3}, {%4,%5,%6,%7}, {%8,%9}, {%0,%1,%2,%3};\n"
                    : "+f"(sacc[nt][0]), "+f"(sacc[nt][1]),
                      "+f"(sacc[nt][2]), "+f"(sacc[nt][3])
                    : "r"(qf[ks][0]), "r"(qf[ks][1]), "r"(qf[ks][2]), "r"(qf[ks][3]),
                      "r"(b0), "r"(b1));
            }
        }

        // ---- online softmax
        float mx0 = sacc[0][0], mx1 = sacc[0][2];
#pragma unroll
        for (int nt = 0; nt < 4; nt++) {
            mx0 = fmaxf(mx0, fmaxf(sacc[nt][0], sacc[nt][1]));
            mx1 = fmaxf(mx1, fmaxf(sacc[nt][2], sacc[nt][3]));
        }
        mx0 = fmaxf(mx0, __shfl_xor_sync(0xffffffffu, mx0, 1));
        mx0 = fmaxf(mx0, __shfl_xor_sync(0xffffffffu, mx0, 2));
        mx1 = fmaxf(mx1, __shfl_xor_sync(0xffffffffu, mx1, 1));
        mx1 = fmaxf(mx1, __shfl_xor_sync(0xffffffffu, mx1, 2));

        float mn0 = fmaxf(m0, mx0), mn1 = fmaxf(m1, mx1);
        float sum0 = 0.f, sum1 = 0.f;
#pragma unroll
        for (int nt = 0; nt < 4; nt++) {
            sacc[nt][0] = __expf(sacc[nt][0] - mn0);
            sacc[nt][1] = __expf(sacc[nt][1] - mn0);
            sacc[nt][2] = __expf(sacc[nt][2] - mn1);
            sacc[nt][3] = __expf(sacc[nt][3] - mn1);
            sum0 += sacc[nt][0] + sacc[nt][1];
            sum1 += sacc[nt][2] + sacc[nt][3];
        }
        sum0 += __shfl_xor_sync(0xffffffffu, sum0, 1);
        sum0 += __shfl_xor_sync(0xffffffffu, sum0, 2);
        sum1 += __shfl_xor_sync(0xffffffffu, sum1, 1);
        sum1 += __shfl_xor_sync(0xffffffffu, sum1, 2);

        float c0 = __expf(m0 - mn0), c1 = __expf(m1 - mn1);
        l0 = l0 * c0 + sum0; l1 = l1 * c1 + sum1;
        m0 = mn0; m1 = mn1;
#pragma unroll
        for (int nt = 0; nt < 16; nt++) {
            acc[nt][0] *= c0; acc[nt][1] *= c0;
            acc[nt][2] *= c1; acc[nt][3] *= c1;
        }

        // ---- P fragments (register repack)
        uint32_t pa[2][4];
#pragma unroll
        for (int k2 = 0; k2 < 2; k2++) {
            pa[k2][0] = pack_h2(sacc[2 * k2][0],     sacc[2 * k2][1]);
            pa[k2][1] = pack_h2(sacc[2 * k2][2],     sacc[2 * k2][3]);
            pa[k2][2] = pack_h2(sacc[2 * k2 + 1][0], sacc[2 * k2 + 1][1]);
            pa[k2][3] = pack_h2(sacc[2 * k2 + 1][2], sacc[2 * k2 + 1][3]);
        }

        // ---- O += P V via ldmatrix.x4.trans B-fragments (V untransposed)
        const int vrow = (lane & 15);
        const int vcol = (lane >> 4) << 3;
#pragma unroll
        for (int k2 = 0; k2 < 2; k2++) {
#pragma unroll
            for (int nt2 = 0; nt2 < 8; nt2++) {
                uint32_t r0, r1, r2, r3;
                uint32_t addr = vsb + (uint32_t)(((k2 * 16 + vrow) * (2 * KROWU)) + nt2 * 16 + vcol) * 2;
                ldsm_x4_t(r0, r1, r2, r3, addr);
                asm volatile(
                    "mma.sync.aligned.m16n8k16.row.col.f32.f16.f16.f32 "
                    "{%0,%1,%2,%3}, {%4,%5,%6,%7}, {%8,%9}, {%0,%1,%2,%3};\n"
                    : "+f"(acc[2 * nt2][0]), "+f"(acc[2 * nt2][1]),
                      "+f"(acc[2 * nt2][2]), "+f"(acc[2 * nt2][3])
                    : "r"(pa[k2][0]), "r"(pa[k2][1]), "r"(pa[k2][2]), "r"(pa[k2][3]),
                      "r"(r0), "r"(r1));
                asm volatile(
                    "mma.sync.aligned.m16n8k16.row.col.f32.f16.f16.f32 "
                    "{%0,%1,%2,%3}, {%4,%5,%6,%7}, {%8,%9}, {%0,%1,%2,%3};\n"
                    : "+f"(acc[2 * nt2 + 1][0]), "+f"(acc[2 * nt2 + 1][1]),
                      "+f"(acc[2 * nt2 + 1][2]), "+f"(acc[2 * nt2 + 1][3])
                    : "r"(pa[k2][0]), "r"(pa[k2][1]), "r"(pa[k2][2]), "r"(pa[k2][3]),
                      "r"(r2), "r"(r3));
            }
        }
    }

    float il0 = 1.f / l0, il1 = 1.f / l1;
    __half* O0 = ob + (size_t)(b * SEQ + qt * 16 + g) * HID + h * HD;
    __half* O1 = O0 + (size_t)8 * HID;
#pragma unroll
    for (int nt = 0; nt < 16; nt++) {
        *(__half2*)(O0 + nt * 8 + 2 * t) = __floats2half2_rn(acc[nt][0] * il0, acc[nt][1] * il0);
        *(__half2*)(O1 + nt * 8 + 2 * t) = __floats2half2_rn(acc[nt][2] * il1, acc[nt][3] * il1);
    }
}

// ---------------------------------------------------------------------------
extern "C" void kernel_launch(void* const* d_in, const int* in_sizes, int n_in,
                              void* d_out, int out_size) {
    const float* x  = (const float*)d_in[0];
    const float* Wq = (const float*)d_in[1];
    const float* Wk = (const float*)d_in[2];
    const float* Wv = (const float*)d_in[3];
    const float* Wo = (const float*)d_in[4];
    float* out = (float*)d_out;

    float*  kvfb; cudaGetSymbolAddress((void**)&kvfb, g_kvfb);
    __half* xh;   cudaGetSymbolAddress((void**)&xh,  g_xh);
    __half* wqh;  cudaGetSymbolAddress((void**)&wqh, g_wqh);
    __half* wkh;  cudaGetSymbolAddress((void**)&wkh, g_wkh);
    __half* wvh;  cudaGetSymbolAddress((void**)&wvh, g_wvh);
    __half* woh;  cudaGetSymbolAddress((void**)&woh, g_woh);
    __half* qh;   cudaGetSymbolAddress((void**)&qh,  g_qh);
    __half* kh;   cudaGetSymbolAddress((void**)&kh,  g_kh);
    __half* vh;   cudaGetSymbolAddress((void**)&vh,  g_vh);
    __half* oh;   cudaGetSymbolAddress((void**)&oh,  g_oh);
    float2* rtab; cudaGetSymbolAddress((void**)&rtab, g_ropetab);

    const size_t off_k = (size_t)MROWS * HID;
    const size_t off_v = off_k + (size_t)MROWS * HD;
    const size_t need  = off_v + (size_t)MROWS * HD;

    float* kout;
    float* vout;
    if ((size_t)out_size >= need) {
        kout = out + off_k;
        vout = out + off_v;
    } else {
        kout = kvfb;
        vout = kvfb + (size_t)MROWS * HD;
    }

    cudaFuncSetAttribute(hgemm_qkv,   cudaFuncAttributeMaxDynamicSharedMemorySize, HG_SMEM);
    cudaFuncSetAttribute(hgemm_plain, cudaFuncAttributeMaxDynamicSharedMemorySize, HG_SMEM);

    // (0) conversions + rope table
    f2h_all<<<dim3(8192, 6), 256>>>(x, Wq, Wk, Wv, Wo);

    // (1) fused QKV projection + rope + fp16 outputs
    hgemm_qkv<<<dim3(18, MROWS / 128), 256, HG_SMEM>>>(
        xh, wqh, wkh, wvh, qh, kout, kh, vout, vh, rtab, HID);

    // (2) flash attention: warp=head, K/V shared across 8 heads/CTA
    flash_fp16<<<dim3(SEQ / 16, NH / 8, NB), 256>>>(qh, kh, vh, oh);

    // (3) O projection — profiled launch
    hgemm_plain<<<dim3(HID / 128, MROWS / 128), 256, HG_SMEM>>>(oh, woh, out, HID, HID);
}